// round 2
// baseline (speedup 1.0000x reference)
#include <cuda_runtime.h>
#include <math.h>

// Problem shape (fixed by reference setup_inputs)
#define B_ROWS 2048
#define E_CODES 512
#define DIM     16384

// Output layout: tuple (loss, quantized_st, perplexity, encodings) flattened
#define OFF_LOSS 0ULL
#define OFF_Q    1ULL
#define OFF_PERP (1ULL + (unsigned long long)B_ROWS * DIM)
#define OFF_ENC  (OFF_PERP + 1ULL)

// Scratch (device globals: no allocations allowed)
__device__ float               g_cb_norm[E_CODES];
__device__ unsigned long long  g_keys[B_ROWS];     // (sortable_dist<<32)|idx
__device__ int                 g_counts[E_CODES];
__device__ double              g_loss_acc;

// ---------------------------------------------------------------------------
__global__ void k_init() {
    int t = blockIdx.x * blockDim.x + threadIdx.x;
    if (t < B_ROWS)  g_keys[t]  = 0xFFFFFFFFFFFFFFFFULL;
    if (t < E_CODES) g_counts[t] = 0;
    if (t == 0)      g_loss_acc  = 0.0;
}

// ---------------------------------------------------------------------------
__device__ __forceinline__ float block_reduce_sum(float v) {
    __shared__ float red[32];
    int lane = threadIdx.x & 31;
    int w    = threadIdx.x >> 5;
    #pragma unroll
    for (int o = 16; o > 0; o >>= 1) v += __shfl_down_sync(0xffffffffu, v, o);
    if (lane == 0) red[w] = v;
    __syncthreads();
    if (w == 0) {
        v = (lane < ((int)blockDim.x >> 5)) ? red[lane] : 0.0f;
        #pragma unroll
        for (int o = 16; o > 0; o >>= 1) v += __shfl_down_sync(0xffffffffu, v, o);
    }
    return v;   // valid on thread 0
}

// ---------------------------------------------------------------------------
// ||e||^2 per codebook row. 512 blocks x 256 threads.
__global__ void k_cbnorm(const float* __restrict__ cb) {
    int e = blockIdx.x;
    const float4* row = (const float4*)(cb + (size_t)e * DIM);
    float s = 0.0f;
    for (int j = threadIdx.x; j < DIM / 4; j += blockDim.x) {
        float4 v = row[j];
        s += v.x * v.x + v.y * v.y + v.z * v.z + v.w * v.w;
    }
    float tot = block_reduce_sum(s);
    if (threadIdx.x == 0) g_cb_norm[e] = tot;
}

// ---------------------------------------------------------------------------
// Fused distance-GEMM + argmin.  score(b,e) = ||e||^2 - 2 * <x_b, e>
// BM=128, BN=64, BK=16, 256 threads (16x16), thread tile 8x4.
#define BM 128
#define BN 64
#define BK 16
#define TM 8
#define TN 4

__global__ void __launch_bounds__(256, 2)
k_gemm_argmin(const float* __restrict__ A, const float* __restrict__ Cb) {
    __shared__ __align__(16) float As[BK][BM + 4];   // stride 132 floats (528B, 16B-aligned)
    __shared__ __align__(16) float Bs[BK][BN + 4];   // stride 68 floats (272B, 16B-aligned)

    const int tid = threadIdx.x;
    const int tx  = tid & 15;        // column group
    const int ty  = tid >> 4;        // row group
    const int m0  = blockIdx.x * BM;
    const int n0  = blockIdx.y * BN;

    float acc[TM][TN];
    #pragma unroll
    for (int i = 0; i < TM; i++)
        #pragma unroll
        for (int j = 0; j < TN; j++) acc[i][j] = 0.0f;

    for (int kk = 0; kk < DIM; kk += BK) {
        // load A tile (128 x 16) as float4 along K, store transposed
        #pragma unroll
        for (int i = 0; i < 2; i++) {
            int id = tid + i * 256;              // 0..511
            int r  = id >> 2;                    // 0..127
            int kq = (id & 3) << 2;              // 0,4,8,12
            float4 v = *(const float4*)(A + (size_t)(m0 + r) * DIM + kk + kq);
            As[kq + 0][r] = v.x;
            As[kq + 1][r] = v.y;
            As[kq + 2][r] = v.z;
            As[kq + 3][r] = v.w;
        }
        // load B tile (64 x 16)
        {
            int r  = tid >> 2;                   // 0..63
            int kq = (tid & 3) << 2;
            float4 v = *(const float4*)(Cb + (size_t)(n0 + r) * DIM + kk + kq);
            Bs[kq + 0][r] = v.x;
            Bs[kq + 1][r] = v.y;
            Bs[kq + 2][r] = v.z;
            Bs[kq + 3][r] = v.w;
        }
        __syncthreads();

        #pragma unroll
        for (int k = 0; k < BK; k++) {
            float a[TM], b[TN];
            *(float4*)&a[0] = *(const float4*)&As[k][ty * TM];
            *(float4*)&a[4] = *(const float4*)&As[k][ty * TM + 4];
            *(float4*)&b[0] = *(const float4*)&Bs[k][tx * TN];
            #pragma unroll
            for (int i = 0; i < TM; i++)
                #pragma unroll
                for (int j = 0; j < TN; j++)
                    acc[i][j] = fmaf(a[i], b[j], acc[i][j]);
        }
        __syncthreads();
    }

    // epilogue: per-row local argmin over this block's 4 columns, merge globally
    float cbn[TN];
    #pragma unroll
    for (int j = 0; j < TN; j++) cbn[j] = g_cb_norm[n0 + tx * TN + j];

    #pragma unroll
    for (int i = 0; i < TM; i++) {
        float best = 3.4e38f;
        int   bidx = 0;
        #pragma unroll
        for (int j = 0; j < TN; j++) {
            float s = cbn[j] - 2.0f * acc[i][j];
            int   e = n0 + tx * TN + j;
            if (s < best) { best = s; bidx = e; }   // ascending j => lowest idx on ties
        }
        unsigned u = __float_as_uint(best);
        u = (u & 0x80000000u) ? ~u : (u | 0x80000000u);   // sortable float
        unsigned long long key = ((unsigned long long)u << 32) | (unsigned)bidx;
        atomicMin(&g_keys[m0 + ty * TM + i], key);
    }
}

// ---------------------------------------------------------------------------
// zero the encodings region (poisoned by harness). Region is 8B-aligned only.
__global__ void k_zero_enc(float* __restrict__ out) {
    float2* p = (float2*)(out + OFF_ENC);
    int n2 = (B_ROWS * E_CODES) / 2;             // 524288
    for (int i = blockIdx.x * blockDim.x + threadIdx.x; i < n2;
         i += gridDim.x * blockDim.x) {
        p[i] = make_float2(0.f, 0.f);
    }
}

// ---------------------------------------------------------------------------
// gather quantized rows + accumulate sum((q-x)^2).  2048 blocks x 256 threads.
// Output region starts at out+1 (only 4B-aligned) -> scalar stores.
__global__ void k_gather(const float* __restrict__ A, const float* __restrict__ Cb,
                         float* __restrict__ out) {
    int b   = blockIdx.x;
    int idx = (int)(g_keys[b] & 0xFFFFFFFFu);
    const float4* q = (const float4*)(Cb + (size_t)idx * DIM);
    const float4* x = (const float4*)(A + (size_t)b * DIM);
    float*        o = out + OFF_Q + (size_t)b * DIM;
    float s = 0.0f;
    for (int j = threadIdx.x; j < DIM / 4; j += blockDim.x) {
        float4 qv = q[j];
        float4 xv = x[j];
        o[4 * j + 0] = qv.x;
        o[4 * j + 1] = qv.y;
        o[4 * j + 2] = qv.z;
        o[4 * j + 3] = qv.w;
        float d0 = qv.x - xv.x, d1 = qv.y - xv.y;
        float d2 = qv.z - xv.z, d3 = qv.w - xv.w;
        s += d0 * d0 + d1 * d1 + d2 * d2 + d3 * d3;
    }
    float tot = block_reduce_sum(s);
    if (threadIdx.x == 0) atomicAdd(&g_loss_acc, (double)tot);
}

// ---------------------------------------------------------------------------
// one-hot scatter + histogram
__global__ void k_scatter(float* __restrict__ out) {
    int b = blockIdx.x * blockDim.x + threadIdx.x;
    if (b < B_ROWS) {
        int idx = (int)(g_keys[b] & 0xFFFFFFFFu);
        out[OFF_ENC + (size_t)b * E_CODES + idx] = 1.0f;
        atomicAdd(&g_counts[idx], 1);
    }
}

// ---------------------------------------------------------------------------
// loss + perplexity
__global__ void k_finalize(float* __restrict__ out) {
    __shared__ float sh[512];
    int e = threadIdx.x;
    float p = (float)g_counts[e] / (float)B_ROWS;
    sh[e] = p * logf(p + 1e-10f);
    __syncthreads();
    for (int s = 256; s > 0; s >>= 1) {
        if (e < s) sh[e] += sh[e + s];
        __syncthreads();
    }
    if (e == 0) {
        out[OFF_PERP] = expf(-sh[0]);
        double mse = g_loss_acc / ((double)B_ROWS * (double)DIM);
        out[OFF_LOSS] = (float)(1.25 * mse);     // q_loss + 0.25*e_loss, both == mse
    }
}

// ---------------------------------------------------------------------------
extern "C" void kernel_launch(void* const* d_in, const int* in_sizes, int n_in,
                              void* d_out, int out_size) {
    const float* inputs   = (const float*)d_in[0];   // [2048, 16384] (B, C*D*H*W)
    const float* codebook = (const float*)d_in[1];   // [512, 16384]
    float* out = (float*)d_out;
    (void)in_sizes; (void)n_in; (void)out_size;

    k_init<<<8, 256>>>();
    k_cbnorm<<<E_CODES, 256>>>(codebook);

    dim3 grid(B_ROWS / BM, E_CODES / BN);            // (16, 8) = 128 blocks
    k_gemm_argmin<<<grid, 256>>>(inputs, codebook);

    k_zero_enc<<<256, 256>>>(out);
    k_gather<<<B_ROWS, 256>>>(inputs, codebook, out);
    k_scatter<<<(B_ROWS + 255) / 256, 256>>>(out);
    k_finalize<<<1, 512>>>(out);
}

// round 3
// speedup vs baseline: 1.0007x; 1.0007x over previous
#include <cuda_runtime.h>
#include <math.h>

// Problem shape (fixed by reference setup_inputs)
#define B_ROWS 2048
#define E_CODES 512
#define DIM     16384

// Output layout: tuple (loss, quantized_st, perplexity, encodings) flattened
#define OFF_LOSS 0ULL
#define OFF_Q    1ULL
#define OFF_PERP (1ULL + (unsigned long long)B_ROWS * DIM)
#define OFF_ENC  (OFF_PERP + 1ULL)

// Scratch (device globals: no allocations allowed)
__device__ float               g_cb_norm[E_CODES];
__device__ unsigned long long  g_keys[B_ROWS];     // (sortable_dist<<32)|idx
__device__ int                 g_counts[E_CODES];
__device__ double              g_loss_acc;

// ---------------------------------------------------------------------------
__global__ void k_init() {
    int t = blockIdx.x * blockDim.x + threadIdx.x;
    if (t < B_ROWS)  g_keys[t]  = 0xFFFFFFFFFFFFFFFFULL;
    if (t < E_CODES) g_counts[t] = 0;
    if (t == 0)      g_loss_acc  = 0.0;
}

// ---------------------------------------------------------------------------
__device__ __forceinline__ float block_reduce_sum(float v) {
    __shared__ float red[32];
    int lane = threadIdx.x & 31;
    int w    = threadIdx.x >> 5;
    #pragma unroll
    for (int o = 16; o > 0; o >>= 1) v += __shfl_down_sync(0xffffffffu, v, o);
    if (lane == 0) red[w] = v;
    __syncthreads();
    if (w == 0) {
        v = (lane < ((int)blockDim.x >> 5)) ? red[lane] : 0.0f;
        #pragma unroll
        for (int o = 16; o > 0; o >>= 1) v += __shfl_down_sync(0xffffffffu, v, o);
    }
    return v;   // valid on thread 0
}

// ---------------------------------------------------------------------------
// ||e||^2 per codebook row. 512 blocks x 256 threads.
__global__ void k_cbnorm(const float* __restrict__ cb) {
    int e = blockIdx.x;
    const float4* row = (const float4*)(cb + (size_t)e * DIM);
    float s = 0.0f;
    for (int j = threadIdx.x; j < DIM / 4; j += blockDim.x) {
        float4 v = row[j];
        s += v.x * v.x + v.y * v.y + v.z * v.z + v.w * v.w;
    }
    float tot = block_reduce_sum(s);
    if (threadIdx.x == 0) g_cb_norm[e] = tot;
}

// ---------------------------------------------------------------------------
// Fused distance-GEMM + argmin.  score(b,e) = ||e||^2 - 2 * <x_b, e>
// BM=128, BN=64, BK=16, 256 threads (16x16), thread tile 8x4.
#define BM 128
#define BN 64
#define BK 16
#define TM 8
#define TN 4

__global__ void __launch_bounds__(256, 2)
k_gemm_argmin(const float* __restrict__ A, const float* __restrict__ Cb) {
    __shared__ __align__(16) float As[BK][BM + 4];   // stride 132 floats (528B, 16B-aligned)
    __shared__ __align__(16) float Bs[BK][BN + 4];   // stride 68 floats (272B, 16B-aligned)

    const int tid = threadIdx.x;
    const int tx  = tid & 15;        // column group
    const int ty  = tid >> 4;        // row group
    const int m0  = blockIdx.x * BM;
    const int n0  = blockIdx.y * BN;

    float acc[TM][TN];
    #pragma unroll
    for (int i = 0; i < TM; i++)
        #pragma unroll
        for (int j = 0; j < TN; j++) acc[i][j] = 0.0f;

    for (int kk = 0; kk < DIM; kk += BK) {
        // load A tile (128 x 16) as float4 along K, store transposed
        #pragma unroll
        for (int i = 0; i < 2; i++) {
            int id = tid + i * 256;              // 0..511
            int r  = id >> 2;                    // 0..127
            int kq = (id & 3) << 2;              // 0,4,8,12
            float4 v = *(const float4*)(A + (size_t)(m0 + r) * DIM + kk + kq);
            As[kq + 0][r] = v.x;
            As[kq + 1][r] = v.y;
            As[kq + 2][r] = v.z;
            As[kq + 3][r] = v.w;
        }
        // load B tile (64 x 16)
        {
            int r  = tid >> 2;                   // 0..63
            int kq = (tid & 3) << 2;
            float4 v = *(const float4*)(Cb + (size_t)(n0 + r) * DIM + kk + kq);
            Bs[kq + 0][r] = v.x;
            Bs[kq + 1][r] = v.y;
            Bs[kq + 2][r] = v.z;
            Bs[kq + 3][r] = v.w;
        }
        __syncthreads();

        #pragma unroll
        for (int k = 0; k < BK; k++) {
            float a[TM], b[TN];
            *(float4*)&a[0] = *(const float4*)&As[k][ty * TM];
            *(float4*)&a[4] = *(const float4*)&As[k][ty * TM + 4];
            *(float4*)&b[0] = *(const float4*)&Bs[k][tx * TN];
            #pragma unroll
            for (int i = 0; i < TM; i++)
                #pragma unroll
                for (int j = 0; j < TN; j++)
                    acc[i][j] = fmaf(a[i], b[j], acc[i][j]);
        }
        __syncthreads();
    }

    // epilogue: per-row local argmin over this block's 4 columns, merge globally
    float cbn[TN];
    #pragma unroll
    for (int j = 0; j < TN; j++) cbn[j] = g_cb_norm[n0 + tx * TN + j];

    #pragma unroll
    for (int i = 0; i < TM; i++) {
        float best = 3.4e38f;
        int   bidx = 0;
        #pragma unroll
        for (int j = 0; j < TN; j++) {
            float s = cbn[j] - 2.0f * acc[i][j];
            int   e = n0 + tx * TN + j;
            if (s < best) { best = s; bidx = e; }   // ascending j => lowest idx on ties
        }
        unsigned u = __float_as_uint(best);
        u = (u & 0x80000000u) ? ~u : (u | 0x80000000u);   // sortable float
        unsigned long long key = ((unsigned long long)u << 32) | (unsigned)bidx;
        atomicMin(&g_keys[m0 + ty * TM + i], key);
    }
}

// ---------------------------------------------------------------------------
// zero the encodings region (poisoned by harness). Region is 8B-aligned only.
__global__ void k_zero_enc(float* __restrict__ out) {
    float2* p = (float2*)(out + OFF_ENC);
    int n2 = (B_ROWS * E_CODES) / 2;             // 524288
    for (int i = blockIdx.x * blockDim.x + threadIdx.x; i < n2;
         i += gridDim.x * blockDim.x) {
        p[i] = make_float2(0.f, 0.f);
    }
}

// ---------------------------------------------------------------------------
// gather quantized rows + accumulate sum((q-x)^2).  2048 blocks x 256 threads.
// Output region starts at out+1 (only 4B-aligned) -> scalar stores.
__global__ void k_gather(const float* __restrict__ A, const float* __restrict__ Cb,
                         float* __restrict__ out) {
    int b   = blockIdx.x;
    int idx = (int)(g_keys[b] & 0xFFFFFFFFu);
    const float4* q = (const float4*)(Cb + (size_t)idx * DIM);
    const float4* x = (const float4*)(A + (size_t)b * DIM);
    float*        o = out + OFF_Q + (size_t)b * DIM;
    float s = 0.0f;
    for (int j = threadIdx.x; j < DIM / 4; j += blockDim.x) {
        float4 qv = q[j];
        float4 xv = x[j];
        o[4 * j + 0] = qv.x;
        o[4 * j + 1] = qv.y;
        o[4 * j + 2] = qv.z;
        o[4 * j + 3] = qv.w;
        float d0 = qv.x - xv.x, d1 = qv.y - xv.y;
        float d2 = qv.z - xv.z, d3 = qv.w - xv.w;
        s += d0 * d0 + d1 * d1 + d2 * d2 + d3 * d3;
    }
    float tot = block_reduce_sum(s);
    if (threadIdx.x == 0) atomicAdd(&g_loss_acc, (double)tot);
}

// ---------------------------------------------------------------------------
// one-hot scatter + histogram
__global__ void k_scatter(float* __restrict__ out) {
    int b = blockIdx.x * blockDim.x + threadIdx.x;
    if (b < B_ROWS) {
        int idx = (int)(g_keys[b] & 0xFFFFFFFFu);
        out[OFF_ENC + (size_t)b * E_CODES + idx] = 1.0f;
        atomicAdd(&g_counts[idx], 1);
    }
}

// ---------------------------------------------------------------------------
// loss + perplexity
__global__ void k_finalize(float* __restrict__ out) {
    __shared__ float sh[512];
    int e = threadIdx.x;
    float p = (float)g_counts[e] / (float)B_ROWS;
    sh[e] = p * logf(p + 1e-10f);
    __syncthreads();
    for (int s = 256; s > 0; s >>= 1) {
        if (e < s) sh[e] += sh[e + s];
        __syncthreads();
    }
    if (e == 0) {
        out[OFF_PERP] = expf(-sh[0]);
        double mse = g_loss_acc / ((double)B_ROWS * (double)DIM);
        out[OFF_LOSS] = (float)(1.25 * mse);     // q_loss + 0.25*e_loss, both == mse
    }
}

// ---------------------------------------------------------------------------
extern "C" void kernel_launch(void* const* d_in, const int* in_sizes, int n_in,
                              void* d_out, int out_size) {
    const float* inputs   = (const float*)d_in[0];   // [2048, 16384] (B, C*D*H*W)
    const float* codebook = (const float*)d_in[1];   // [512, 16384]
    float* out = (float*)d_out;
    (void)in_sizes; (void)n_in; (void)out_size;

    k_init<<<8, 256>>>();
    k_cbnorm<<<E_CODES, 256>>>(codebook);

    dim3 grid(B_ROWS / BM, E_CODES / BN);            // (16, 8) = 128 blocks
    k_gemm_argmin<<<grid, 256>>>(inputs, codebook);

    k_zero_enc<<<256, 256>>>(out);
    k_gather<<<B_ROWS, 256>>>(inputs, codebook, out);
    k_scatter<<<(B_ROWS + 255) / 256, 256>>>(out);
    k_finalize<<<1, 512>>>(out);
}

// round 5
// speedup vs baseline: 2.8015x; 2.7995x over previous
#include <cuda_runtime.h>
#include <cuda_bf16.h>
#include <math.h>
#include <stdint.h>

// Problem shape (fixed by reference setup_inputs)
#define B_ROWS 2048
#define E_CODES 512
#define DIM     16384

// Output layout: tuple (loss, quantized_st, perplexity, encodings) flattened
#define OFF_LOSS 0ULL
#define OFF_Q    1ULL
#define OFF_PERP (1ULL + (unsigned long long)B_ROWS * DIM)
#define OFF_ENC  (OFF_PERP + 1ULL)

// ---------------------------------------------------------------------------
// Scratch (device globals: no allocations allowed)
__device__ __align__(16) __nv_bfloat16 g_Ah[(size_t)B_ROWS * DIM];
__device__ __align__(16) __nv_bfloat16 g_Al[(size_t)B_ROWS * DIM];
__device__ __align__(16) __nv_bfloat16 g_Bh[(size_t)E_CODES * DIM];
__device__ __align__(16) __nv_bfloat16 g_Bl[(size_t)E_CODES * DIM];
__device__ __align__(16) float         g_Dpart[2ULL * B_ROWS * E_CODES]; // 8 MB
__device__ float               g_cb_norm[E_CODES];
__device__ unsigned long long  g_keys[B_ROWS];
__device__ int                 g_counts[E_CODES];
__device__ double              g_loss_acc;

// ---------------------------------------------------------------------------
__device__ __forceinline__ uint32_t smem_u32(const void* p) {
    uint32_t a;
    asm("{ .reg .u64 t; cvta.to.shared.u64 t, %1; cvt.u32.u64 %0, t; }" : "=r"(a) : "l"(p));
    return a;
}
#define CP_ASYNC16(dst, src) \
    asm volatile("cp.async.cg.shared.global [%0], [%1], 16;" :: "r"(dst), "l"(src) : "memory")
#define CP_COMMIT() asm volatile("cp.async.commit_group;" ::: "memory")
#define CP_WAIT2()  asm volatile("cp.async.wait_group 2;" ::: "memory")

#define LDSM_X4(r, addr)                                                        \
    asm volatile("ldmatrix.sync.aligned.m8n8.x4.shared.b16 {%0,%1,%2,%3}, [%4];" \
        : "=r"((r)[0]), "=r"((r)[1]), "=r"((r)[2]), "=r"((r)[3]) : "r"(addr))

#define MMA_BF16(d, a, b)                                                       \
    asm volatile("mma.sync.aligned.m16n8k16.row.col.f32.bf16.bf16.f32 "         \
        "{%0,%1,%2,%3}, {%4,%5,%6,%7}, {%8,%9}, {%0,%1,%2,%3};"                 \
        : "+f"((d)[0]), "+f"((d)[1]), "+f"((d)[2]), "+f"((d)[3])                \
        : "r"((a)[0]), "r"((a)[1]), "r"((a)[2]), "r"((a)[3]),                   \
          "r"((b)[0]), "r"((b)[1]))

// ---------------------------------------------------------------------------
__global__ void k_init() {
    int t = blockIdx.x * blockDim.x + threadIdx.x;
    if (t < E_CODES) g_counts[t] = 0;
    if (t == 0)      g_loss_acc  = 0.0;
}

// ---------------------------------------------------------------------------
__device__ __forceinline__ float block_reduce_sum(float v) {
    __shared__ float red[32];
    int lane = threadIdx.x & 31;
    int w    = threadIdx.x >> 5;
    #pragma unroll
    for (int o = 16; o > 0; o >>= 1) v += __shfl_down_sync(0xffffffffu, v, o);
    if (lane == 0) red[w] = v;
    __syncthreads();
    if (w == 0) {
        v = (lane < ((int)blockDim.x >> 5)) ? red[lane] : 0.0f;
        #pragma unroll
        for (int o = 16; o > 0; o >>= 1) v += __shfl_down_sync(0xffffffffu, v, o);
    }
    return v;
}

// ---------------------------------------------------------------------------
// split fp32 -> bf16 hi/lo for inputs and codebook
__global__ void k_convert(const float* __restrict__ A, const float* __restrict__ Cb) {
    const size_t nA = (size_t)B_ROWS * DIM / 4;
    const size_t nB = (size_t)E_CODES * DIM / 4;
    for (size_t i = blockIdx.x * (size_t)blockDim.x + threadIdx.x; i < nA + nB;
         i += (size_t)gridDim.x * blockDim.x) {
        float4 v = (i < nA) ? ((const float4*)A)[i] : ((const float4*)Cb)[i - nA];
        __nv_bfloat16 h0 = __float2bfloat16(v.x), h1 = __float2bfloat16(v.y);
        __nv_bfloat16 h2 = __float2bfloat16(v.z), h3 = __float2bfloat16(v.w);
        __nv_bfloat16 l0 = __float2bfloat16(v.x - __bfloat162float(h0));
        __nv_bfloat16 l1 = __float2bfloat16(v.y - __bfloat162float(h1));
        __nv_bfloat16 l2 = __float2bfloat16(v.z - __bfloat162float(h2));
        __nv_bfloat16 l3 = __float2bfloat16(v.w - __bfloat162float(h3));
        __nv_bfloat162 ha = __halves2bfloat162(h0, h1), hb = __halves2bfloat162(h2, h3);
        __nv_bfloat162 la = __halves2bfloat162(l0, l1), lb = __halves2bfloat162(l2, l3);
        uint2 hp, lp;
        hp.x = *(unsigned*)&ha; hp.y = *(unsigned*)&hb;
        lp.x = *(unsigned*)&la; lp.y = *(unsigned*)&lb;
        if (i < nA) {
            *(uint2*)(g_Ah + 4 * i) = hp;
            *(uint2*)(g_Al + 4 * i) = lp;
        } else {
            size_t j = i - nA;
            *(uint2*)(g_Bh + 4 * j) = hp;
            *(uint2*)(g_Bl + 4 * j) = lp;
        }
    }
}

// ---------------------------------------------------------------------------
// ||e||^2 per codebook row (fp32, from original codebook)
__global__ void k_cbnorm(const float* __restrict__ cb) {
    int e = blockIdx.x;
    const float4* row = (const float4*)(cb + (size_t)e * DIM);
    float s = 0.0f;
    for (int j = threadIdx.x; j < DIM / 4; j += blockDim.x) {
        float4 v = row[j];
        s += v.x * v.x + v.y * v.y + v.z * v.z + v.w * v.w;
    }
    float tot = block_reduce_sum(s);
    if (threadIdx.x == 0) g_cb_norm[e] = tot;
}

// ---------------------------------------------------------------------------
// Split-bf16 GEMM via mma.sync (HMMA): dot(x_b, e_n) fp32 accum.
// CTA tile 128x128, 8 warps (warp tile 32x64), KC=32, 4-stage cp.async.
#define MT      128
#define NT      128
#define KC      32
#define NSTAGE  4
#define KHALF   (DIM / 2)
#define ITERS   (KHALF / KC)                 // 256
#define ROW_B   80                           // 64B data + 16B pad (16B multiple)
#define TILE_B  (128 * ROW_B)                // 10240 B
#define STAGE_B (4 * TILE_B)                 // 40960 B (Ah, Al, Bh, Bl)
#define SMEM_TOTAL (NSTAGE * STAGE_B)        // 163840 B

__device__ __forceinline__ void load_stage(uint32_t sb, int st, int it, int m0, int n0,
                                           int kz, int tid) {
    const int kbase = kz + it * KC;
    #pragma unroll
    for (int j = 0; j < 8; j++) {
        int idx = tid + j * 256;             // 0..2047
        int t   = idx >> 9;                  // 0:Ah 1:Al 2:Bh 3:Bl
        int w   = idx & 511;
        int r   = w >> 2;                    // row 0..127
        int c   = w & 3;                     // 16B chunk 0..3
        const __nv_bfloat16* src;
        if (t == 0)      src = g_Ah + (size_t)(m0 + r) * DIM;
        else if (t == 1) src = g_Al + (size_t)(m0 + r) * DIM;
        else if (t == 2) src = g_Bh + (size_t)(n0 + r) * DIM;
        else             src = g_Bl + (size_t)(n0 + r) * DIM;
        src += kbase + c * 8;
        uint32_t dst = sb + st * STAGE_B + t * TILE_B + r * ROW_B + c * 16;
        CP_ASYNC16(dst, src);
    }
}

__global__ void __launch_bounds__(256, 1) k_mma() {
    extern __shared__ __align__(16) char smem[];
    const uint32_t sb = smem_u32(smem);
    const int tid  = threadIdx.x;
    const int wid  = tid >> 5;
    const int lane = tid & 31;
    const int wm   = wid & 3;                // m block (32 rows)
    const int wn   = wid >> 2;               // n block (64 cols)
    const int m0   = blockIdx.x * MT;
    const int n0   = blockIdx.y * NT;
    const int kz   = blockIdx.z * KHALF;

    float acc[2][8][4];
    #pragma unroll
    for (int mi = 0; mi < 2; mi++)
        #pragma unroll
        for (int nj = 0; nj < 8; nj++)
            #pragma unroll
            for (int q = 0; q < 4; q++) acc[mi][nj][q] = 0.0f;

    // prologue: stages 0..2
    #pragma unroll
    for (int p = 0; p < NSTAGE - 1; p++) { load_stage(sb, p, p, m0, n0, kz, tid); CP_COMMIT(); }

    const uint32_t lrow = (lane & 15);
    const uint32_t lcol = (lane >> 4) * 16;

    for (int i = 0; i < ITERS; i++) {
        const int st = i & (NSTAGE - 1);
        CP_WAIT2();
        __syncthreads();
        if (i + NSTAGE - 1 < ITERS) load_stage(sb, (st + NSTAGE - 1) & (NSTAGE - 1),
                                               i + NSTAGE - 1, m0, n0, kz, tid);
        CP_COMMIT();

        const uint32_t s0 = sb + st * STAGE_B;
        #pragma unroll
        for (int ks = 0; ks < 2; ks++) {
            const uint32_t ko = ks * 32 + lcol;   // bytes within row
            uint32_t ah[2][4], al[2][4];
            #pragma unroll
            for (int mi = 0; mi < 2; mi++) {
                uint32_t r = (wm * 32 + mi * 16 + lrow) * ROW_B + ko;
                LDSM_X4(ah[mi], s0 + 0 * TILE_B + r);
                LDSM_X4(al[mi], s0 + 1 * TILE_B + r);
            }
            uint32_t bh[8][2], bl[8][2];
            #pragma unroll
            for (int nq = 0; nq < 4; nq++) {
                uint32_t r = (wn * 64 + nq * 16 + lrow) * ROW_B + ko;
                uint32_t t[4];
                LDSM_X4(t, s0 + 2 * TILE_B + r);
                bh[2 * nq][0] = t[0]; bh[2 * nq][1] = t[2];
                bh[2 * nq + 1][0] = t[1]; bh[2 * nq + 1][1] = t[3];
                LDSM_X4(t, s0 + 3 * TILE_B + r);
                bl[2 * nq][0] = t[0]; bl[2 * nq][1] = t[2];
                bl[2 * nq + 1][0] = t[1]; bl[2 * nq + 1][1] = t[3];
            }
            #pragma unroll
            for (int mi = 0; mi < 2; mi++)
                #pragma unroll
                for (int nj = 0; nj < 8; nj++) {
                    MMA_BF16(acc[mi][nj], ah[mi], bh[nj]);
                    MMA_BF16(acc[mi][nj], ah[mi], bl[nj]);
                    MMA_BF16(acc[mi][nj], al[mi], bh[nj]);
                }
        }
    }

    // epilogue: write partial dots
    #pragma unroll
    for (int mi = 0; mi < 2; mi++) {
        #pragma unroll
        for (int nj = 0; nj < 8; nj++) {
            int row = m0 + wm * 32 + mi * 16 + (lane >> 2);
            int col = n0 + wn * 64 + nj * 8 + (lane & 3) * 2;
            float* d = &g_Dpart[((size_t)blockIdx.z * B_ROWS + row) * E_CODES + col];
            float2 v0 = make_float2(acc[mi][nj][0], acc[mi][nj][1]);
            float2 v1 = make_float2(acc[mi][nj][2], acc[mi][nj][3]);
            *(float2*)d = v0;
            *(float2*)(d + 8 * E_CODES) = v1;
        }
    }
}

// ---------------------------------------------------------------------------
// merge K-halves, compute score, argmin per row (one warp per row)
__global__ void k_argmin() {
    const int row  = blockIdx.x * 8 + (threadIdx.x >> 5);
    const int lane = threadIdx.x & 31;
    const float* d0 = &g_Dpart[(size_t)row * E_CODES];
    const float* d1 = &g_Dpart[((size_t)B_ROWS + row) * E_CODES];
    float best = 3.4e38f;
    int   bi   = 0;
    #pragma unroll
    for (int j = 0; j < 16; j++) {
        int   e = j * 32 + lane;
        float s = g_cb_norm[e] - 2.0f * (d0[e] + d1[e]);
        if (s < best) { best = s; bi = e; }
    }
    unsigned u = __float_as_uint(best);
    u = (u & 0x80000000u) ? ~u : (u | 0x80000000u);
    unsigned long long key = ((unsigned long long)u << 32) | (unsigned)bi;
    #pragma unroll
    for (int o = 16; o > 0; o >>= 1) {
        unsigned long long other = __shfl_xor_sync(0xffffffffu, key, o);
        key = (other < key) ? other : key;
    }
    if (lane == 0) g_keys[row] = key;
}

// ---------------------------------------------------------------------------
// zero the encodings region (poisoned by harness). Region is 8B-aligned only.
__global__ void k_zero_enc(float* __restrict__ out) {
    float2* p = (float2*)(out + OFF_ENC);
    int n2 = (B_ROWS * E_CODES) / 2;
    for (int i = blockIdx.x * blockDim.x + threadIdx.x; i < n2;
         i += gridDim.x * blockDim.x) {
        p[i] = make_float2(0.f, 0.f);
    }
}

// ---------------------------------------------------------------------------
// gather quantized rows + accumulate sum((q-x)^2). Output at out+1: scalar stores.
__global__ void k_gather(const float* __restrict__ A, const float* __restrict__ Cb,
                         float* __restrict__ out) {
    int b   = blockIdx.x;
    int idx = (int)(g_keys[b] & 0xFFFFFFFFu);
    const float4* q = (const float4*)(Cb + (size_t)idx * DIM);
    const float4* x = (const float4*)(A + (size_t)b * DIM);
    float*        o = out + OFF_Q + (size_t)b * DIM;
    float s = 0.0f;
    for (int j = threadIdx.x; j < DIM / 4; j += blockDim.x) {
        float4 qv = q[j];
        float4 xv = x[j];
        o[4 * j + 0] = qv.x;
        o[4 * j + 1] = qv.y;
        o[4 * j + 2] = qv.z;
        o[4 * j + 3] = qv.w;
        float d0 = qv.x - xv.x, d1 = qv.y - xv.y;
        float d2 = qv.z - xv.z, d3 = qv.w - xv.w;
        s += d0 * d0 + d1 * d1 + d2 * d2 + d3 * d3;
    }
    float tot = block_reduce_sum(s);
    if (threadIdx.x == 0) atomicAdd(&g_loss_acc, (double)tot);
}

// ---------------------------------------------------------------------------
__global__ void k_scatter(float* __restrict__ out) {
    int b = blockIdx.x * blockDim.x + threadIdx.x;
    if (b < B_ROWS) {
        int idx = (int)(g_keys[b] & 0xFFFFFFFFu);
        out[OFF_ENC + (size_t)b * E_CODES + idx] = 1.0f;
        atomicAdd(&g_counts[idx], 1);
    }
}

// ---------------------------------------------------------------------------
__global__ void k_finalize(float* __restrict__ out) {
    __shared__ float sh[512];
    int e = threadIdx.x;
    float p = (float)g_counts[e] / (float)B_ROWS;
    sh[e] = p * logf(p + 1e-10f);
    __syncthreads();
    for (int s = 256; s > 0; s >>= 1) {
        if (e < s) sh[e] += sh[e + s];
        __syncthreads();
    }
    if (e == 0) {
        out[OFF_PERP] = expf(-sh[0]);
        double mse = g_loss_acc / ((double)B_ROWS * (double)DIM);
        out[OFF_LOSS] = (float)(1.25 * mse);
    }
}

// ---------------------------------------------------------------------------
extern "C" void kernel_launch(void* const* d_in, const int* in_sizes, int n_in,
                              void* d_out, int out_size) {
    const float* inputs   = (const float*)d_in[0];   // [2048, 16384]
    const float* codebook = (const float*)d_in[1];   // [512, 16384]
    float* out = (float*)d_out;
    (void)in_sizes; (void)n_in; (void)out_size;

    static int smem_set = 0;
    if (!smem_set) {
        cudaFuncSetAttribute(k_mma, cudaFuncAttributeMaxDynamicSharedMemorySize, SMEM_TOTAL);
        smem_set = 1;
    }

    k_init<<<8, 256>>>();
    k_convert<<<2048, 256>>>(inputs, codebook);
    k_cbnorm<<<E_CODES, 256>>>(codebook);

    dim3 grid(B_ROWS / MT, E_CODES / NT, 2);         // (16, 4, 2) = 128 CTAs
    k_mma<<<grid, 256, SMEM_TOTAL>>>();

    k_argmin<<<B_ROWS / 8, 256>>>();
    k_zero_enc<<<256, 256>>>(out);
    k_gather<<<B_ROWS, 256>>>(inputs, codebook, out);
    k_scatter<<<(B_ROWS + 255) / 256, 256>>>(out);
    k_finalize<<<1, 512>>>(out);
}

// round 6
// speedup vs baseline: 2.8599x; 1.0209x over previous
#include <cuda_runtime.h>
#include <cuda_bf16.h>
#include <math.h>
#include <stdint.h>

// Problem shape (fixed by reference setup_inputs)
#define B_ROWS 2048
#define E_CODES 512
#define DIM     16384

// Output layout: tuple (loss, quantized_st, perplexity, encodings) flattened
#define OFF_LOSS 0ULL
#define OFF_Q    1ULL
#define OFF_PERP (1ULL + (unsigned long long)B_ROWS * DIM)
#define OFF_ENC  (OFF_PERP + 1ULL)

#define KSPLIT 4

// ---------------------------------------------------------------------------
// Scratch (device globals: no allocations allowed)
__device__ __align__(16) __nv_bfloat16 g_Ah[(size_t)B_ROWS * DIM];
__device__ __align__(16) __nv_bfloat16 g_Al[(size_t)B_ROWS * DIM];
__device__ __align__(16) __nv_bfloat16 g_Bh[(size_t)E_CODES * DIM];
__device__ __align__(16) __nv_bfloat16 g_Bl[(size_t)E_CODES * DIM];
__device__ __align__(16) float         g_Dpart[(size_t)KSPLIT * B_ROWS * E_CODES]; // 16 MB
__device__ float               g_cb_norm[E_CODES];
__device__ unsigned long long  g_keys[B_ROWS];
__device__ int                 g_counts[E_CODES];
__device__ double              g_loss_acc;

// ---------------------------------------------------------------------------
__device__ __forceinline__ uint32_t smem_u32(const void* p) {
    uint32_t a;
    asm("{ .reg .u64 t; cvta.to.shared.u64 t, %1; cvt.u32.u64 %0, t; }" : "=r"(a) : "l"(p));
    return a;
}
#define CP_ASYNC16(dst, src) \
    asm volatile("cp.async.cg.shared.global [%0], [%1], 16;" :: "r"(dst), "l"(src) : "memory")
#define CP_COMMIT() asm volatile("cp.async.commit_group;" ::: "memory")
#define CP_WAIT1()  asm volatile("cp.async.wait_group 1;" ::: "memory")

#define LDSM_X4(r, addr)                                                        \
    asm volatile("ldmatrix.sync.aligned.m8n8.x4.shared.b16 {%0,%1,%2,%3}, [%4];" \
        : "=r"((r)[0]), "=r"((r)[1]), "=r"((r)[2]), "=r"((r)[3]) : "r"(addr))

#define MMA_BF16(d, a0, a1, a2, a3, b0, b1)                                     \
    asm volatile("mma.sync.aligned.m16n8k16.row.col.f32.bf16.bf16.f32 "         \
        "{%0,%1,%2,%3}, {%4,%5,%6,%7}, {%8,%9}, {%0,%1,%2,%3};"                 \
        : "+f"((d)[0]), "+f"((d)[1]), "+f"((d)[2]), "+f"((d)[3])                \
        : "r"(a0), "r"(a1), "r"(a2), "r"(a3), "r"(b0), "r"(b1))

// SW128 swizzle (128-byte rows): XOR row bits [7:9] into 16B-chunk bits [4:6]
__device__ __forceinline__ uint32_t swz(uint32_t off) { return off ^ ((off >> 3) & 0x70); }

// ---------------------------------------------------------------------------
__global__ void k_init() {
    int t = blockIdx.x * blockDim.x + threadIdx.x;
    if (t < E_CODES) g_counts[t] = 0;
    if (t == 0)      g_loss_acc  = 0.0;
}

// ---------------------------------------------------------------------------
__device__ __forceinline__ float block_reduce_sum(float v) {
    __shared__ float red[32];
    int lane = threadIdx.x & 31;
    int w    = threadIdx.x >> 5;
    #pragma unroll
    for (int o = 16; o > 0; o >>= 1) v += __shfl_down_sync(0xffffffffu, v, o);
    if (lane == 0) red[w] = v;
    __syncthreads();
    if (w == 0) {
        v = (lane < ((int)blockDim.x >> 5)) ? red[lane] : 0.0f;
        #pragma unroll
        for (int o = 16; o > 0; o >>= 1) v += __shfl_down_sync(0xffffffffu, v, o);
    }
    return v;
}

// ---------------------------------------------------------------------------
// split fp32 -> bf16 hi/lo for inputs and codebook
__global__ void k_convert(const float* __restrict__ A, const float* __restrict__ Cb) {
    const size_t nA = (size_t)B_ROWS * DIM / 4;
    const size_t nB = (size_t)E_CODES * DIM / 4;
    for (size_t i = blockIdx.x * (size_t)blockDim.x + threadIdx.x; i < nA + nB;
         i += (size_t)gridDim.x * blockDim.x) {
        float4 v = (i < nA) ? ((const float4*)A)[i] : ((const float4*)Cb)[i - nA];
        __nv_bfloat16 h0 = __float2bfloat16(v.x), h1 = __float2bfloat16(v.y);
        __nv_bfloat16 h2 = __float2bfloat16(v.z), h3 = __float2bfloat16(v.w);
        __nv_bfloat16 l0 = __float2bfloat16(v.x - __bfloat162float(h0));
        __nv_bfloat16 l1 = __float2bfloat16(v.y - __bfloat162float(h1));
        __nv_bfloat16 l2 = __float2bfloat16(v.z - __bfloat162float(h2));
        __nv_bfloat16 l3 = __float2bfloat16(v.w - __bfloat162float(h3));
        __nv_bfloat162 ha = __halves2bfloat162(h0, h1), hb = __halves2bfloat162(h2, h3);
        __nv_bfloat162 la = __halves2bfloat162(l0, l1), lb = __halves2bfloat162(l2, l3);
        uint2 hp, lp;
        hp.x = *(unsigned*)&ha; hp.y = *(unsigned*)&hb;
        lp.x = *(unsigned*)&la; lp.y = *(unsigned*)&lb;
        if (i < nA) {
            *(uint2*)(g_Ah + 4 * i) = hp;
            *(uint2*)(g_Al + 4 * i) = lp;
        } else {
            size_t j = i - nA;
            *(uint2*)(g_Bh + 4 * j) = hp;
            *(uint2*)(g_Bl + 4 * j) = lp;
        }
    }
}

// ---------------------------------------------------------------------------
// ||e||^2 per codebook row (fp32, from original codebook)
__global__ void k_cbnorm(const float* __restrict__ cb) {
    int e = blockIdx.x;
    const float4* row = (const float4*)(cb + (size_t)e * DIM);
    float s = 0.0f;
    for (int j = threadIdx.x; j < DIM / 4; j += blockDim.x) {
        float4 v = row[j];
        s += v.x * v.x + v.y * v.y + v.z * v.z + v.w * v.w;
    }
    float tot = block_reduce_sum(s);
    if (threadIdx.x == 0) g_cb_norm[e] = tot;
}

// ---------------------------------------------------------------------------
// Split-bf16 GEMM via mma.sync (HMMA): dot(x_b, e_n) fp32 accum.
// CTA tile 128x128, 8 warps (warp tile 32x64), KC=32, 3-stage cp.async,
// SW128-swizzled 128B rows packing hi|lo -> 96KB smem -> 2 CTAs/SM.
#define MT      128
#define NT      128
#define KC      32
#define NSTAGE  3
#define KSLICE  (DIM / KSPLIT)               // 4096
#define ITERS   (KSLICE / KC)                // 128
#define TILE_B  (128 * 128)                  // 16 KB: 128 rows x (hi 64B | lo 64B)
#define STAGE_B (2 * TILE_B)                 // 32 KB (A tile, B tile)
#define SMEM_TOTAL (NSTAGE * STAGE_B)        // 98304 B

__device__ __forceinline__ void load_stage(uint32_t sb, int st, int it, int m0, int n0,
                                           int kz, int tid) {
    const int kbase = kz + it * KC;
    #pragma unroll
    for (int j = 0; j < 8; j++) {
        int idx = tid + j * 256;             // 0..2047
        int t   = idx >> 10;                 // 0:A  1:B
        int w   = idx & 1023;
        int r   = w >> 3;                    // row 0..127
        int c   = w & 7;                     // 16B chunk; c<4 -> hi, c>=4 -> lo
        const __nv_bfloat16* src;
        if (t == 0) src = ((c < 4) ? g_Ah : g_Al) + (size_t)(m0 + r) * DIM;
        else        src = ((c < 4) ? g_Bh : g_Bl) + (size_t)(n0 + r) * DIM;
        src += kbase + (c & 3) * 8;
        uint32_t dst = sb + st * STAGE_B + t * TILE_B + swz(r * 128 + c * 16);
        CP_ASYNC16(dst, src);
    }
}

__global__ void __launch_bounds__(256, 2) k_mma() {
    extern __shared__ __align__(128) char smem[];
    const uint32_t sb = smem_u32(smem);
    const int tid  = threadIdx.x;
    const int wid  = tid >> 5;
    const int lane = tid & 31;
    const int wm   = wid & 3;                // m block (32 rows)
    const int wn   = wid >> 2;               // n block (64 cols)
    const int m0   = blockIdx.x * MT;
    const int n0   = blockIdx.y * NT;
    const int kz   = blockIdx.z * KSLICE;

    float acc[2][8][4];
    #pragma unroll
    for (int mi = 0; mi < 2; mi++)
        #pragma unroll
        for (int nj = 0; nj < 8; nj++)
            #pragma unroll
            for (int q = 0; q < 4; q++) acc[mi][nj][q] = 0.0f;

    // prologue: stages 0,1
    #pragma unroll
    for (int p = 0; p < NSTAGE - 1; p++) { load_stage(sb, p, p, m0, n0, kz, tid); CP_COMMIT(); }

    const uint32_t lrow = (lane & 15);
    const uint32_t lcol = (lane >> 4) * 16;

    for (int i = 0; i < ITERS; i++) {
        const int st = i % NSTAGE;
        CP_WAIT1();
        __syncthreads();
        if (i + NSTAGE - 1 < ITERS)
            load_stage(sb, (i + NSTAGE - 1) % NSTAGE, i + NSTAGE - 1, m0, n0, kz, tid);
        CP_COMMIT();

        const uint32_t s0 = sb + st * STAGE_B;
        #pragma unroll
        for (int ks = 0; ks < 2; ks++) {
            const uint32_t ko = ks * 32 + lcol;      // hi bytes 0..63; lo at +64
            uint32_t ah[2][4], al[2][4];
            #pragma unroll
            for (int mi = 0; mi < 2; mi++) {
                uint32_t ro = (wm * 32 + mi * 16 + lrow) * 128;
                LDSM_X4(ah[mi], s0 + swz(ro + ko));
                LDSM_X4(al[mi], s0 + swz(ro + 64 + ko));
            }
            #pragma unroll
            for (int nq = 0; nq < 4; nq++) {
                uint32_t ro = (wn * 64 + nq * 16 + lrow) * 128;
                uint32_t th[4], tl[4];
                LDSM_X4(th, s0 + TILE_B + swz(ro + ko));
                LDSM_X4(tl, s0 + TILE_B + swz(ro + 64 + ko));
                #pragma unroll
                for (int mi = 0; mi < 2; mi++) {
                    float* a0 = acc[mi][2 * nq];
                    float* a1 = acc[mi][2 * nq + 1];
                    MMA_BF16(a0, ah[mi][0], ah[mi][1], ah[mi][2], ah[mi][3], th[0], th[2]);
                    MMA_BF16(a1, ah[mi][0], ah[mi][1], ah[mi][2], ah[mi][3], th[1], th[3]);
                    MMA_BF16(a0, ah[mi][0], ah[mi][1], ah[mi][2], ah[mi][3], tl[0], tl[2]);
                    MMA_BF16(a1, ah[mi][0], ah[mi][1], ah[mi][2], ah[mi][3], tl[1], tl[3]);
                    MMA_BF16(a0, al[mi][0], al[mi][1], al[mi][2], al[mi][3], th[0], th[2]);
                    MMA_BF16(a1, al[mi][0], al[mi][1], al[mi][2], al[mi][3], th[1], th[3]);
                }
            }
        }
    }

    // epilogue: write partial dots
    #pragma unroll
    for (int mi = 0; mi < 2; mi++) {
        #pragma unroll
        for (int nj = 0; nj < 8; nj++) {
            int row = m0 + wm * 32 + mi * 16 + (lane >> 2);
            int col = n0 + wn * 64 + nj * 8 + (lane & 3) * 2;
            float* d = &g_Dpart[((size_t)blockIdx.z * B_ROWS + row) * E_CODES + col];
            *(float2*)d = make_float2(acc[mi][nj][0], acc[mi][nj][1]);
            *(float2*)(d + 8 * E_CODES) = make_float2(acc[mi][nj][2], acc[mi][nj][3]);
        }
    }
}

// ---------------------------------------------------------------------------
// merge K-slices, compute score, argmin per row (one warp per row)
__global__ void k_argmin() {
    const int row  = blockIdx.x * 8 + (threadIdx.x >> 5);
    const int lane = threadIdx.x & 31;
    const size_t SL = (size_t)B_ROWS * E_CODES;
    const float* d = &g_Dpart[(size_t)row * E_CODES];
    float best = 3.4e38f;
    int   bi   = 0;
    #pragma unroll
    for (int j = 0; j < 16; j++) {
        int   e = j * 32 + lane;
        float dot = 0.0f;
        #pragma unroll
        for (int z = 0; z < KSPLIT; z++) dot += d[z * SL + e];
        float s = g_cb_norm[e] - 2.0f * dot;
        if (s < best) { best = s; bi = e; }
    }
    unsigned u = __float_as_uint(best);
    u = (u & 0x80000000u) ? ~u : (u | 0x80000000u);
    unsigned long long key = ((unsigned long long)u << 32) | (unsigned)bi;
    #pragma unroll
    for (int o = 16; o > 0; o >>= 1) {
        unsigned long long other = __shfl_xor_sync(0xffffffffu, key, o);
        key = (other < key) ? other : key;
    }
    if (lane == 0) g_keys[row] = key;
}

// ---------------------------------------------------------------------------
// zero the encodings region (poisoned by harness). Region is 8B-aligned only.
__global__ void k_zero_enc(float* __restrict__ out) {
    float2* p = (float2*)(out + OFF_ENC);
    int n2 = (B_ROWS * E_CODES) / 2;
    for (int i = blockIdx.x * blockDim.x + threadIdx.x; i < n2;
         i += gridDim.x * blockDim.x) {
        p[i] = make_float2(0.f, 0.f);
    }
}

// ---------------------------------------------------------------------------
// gather quantized rows + accumulate sum((q-x)^2). Output at out+1: scalar stores.
__global__ void k_gather(const float* __restrict__ A, const float* __restrict__ Cb,
                         float* __restrict__ out) {
    int b   = blockIdx.x;
    int idx = (int)(g_keys[b] & 0xFFFFFFFFu);
    const float4* q = (const float4*)(Cb + (size_t)idx * DIM);
    const float4* x = (const float4*)(A + (size_t)b * DIM);
    float*        o = out + OFF_Q + (size_t)b * DIM;
    float s = 0.0f;
    for (int j = threadIdx.x; j < DIM / 4; j += blockDim.x) {
        float4 qv = q[j];
        float4 xv = x[j];
        o[4 * j + 0] = qv.x;
        o[4 * j + 1] = qv.y;
        o[4 * j + 2] = qv.z;
        o[4 * j + 3] = qv.w;
        float d0 = qv.x - xv.x, d1 = qv.y - xv.y;
        float d2 = qv.z - xv.z, d3 = qv.w - xv.w;
        s += d0 * d0 + d1 * d1 + d2 * d2 + d3 * d3;
    }
    float tot = block_reduce_sum(s);
    if (threadIdx.x == 0) atomicAdd(&g_loss_acc, (double)tot);
}

// ---------------------------------------------------------------------------
__global__ void k_scatter(float* __restrict__ out) {
    int b = blockIdx.x * blockDim.x + threadIdx.x;
    if (b < B_ROWS) {
        int idx = (int)(g_keys[b] & 0xFFFFFFFFu);
        out[OFF_ENC + (size_t)b * E_CODES + idx] = 1.0f;
        atomicAdd(&g_counts[idx], 1);
    }
}

// ---------------------------------------------------------------------------
__global__ void k_finalize(float* __restrict__ out) {
    __shared__ float sh[512];
    int e = threadIdx.x;
    float p = (float)g_counts[e] / (float)B_ROWS;
    sh[e] = p * logf(p + 1e-10f);
    __syncthreads();
    for (int s = 256; s > 0; s >>= 1) {
        if (e < s) sh[e] += sh[e + s];
        __syncthreads();
    }
    if (e == 0) {
        out[OFF_PERP] = expf(-sh[0]);
        double mse = g_loss_acc / ((double)B_ROWS * (double)DIM);
        out[OFF_LOSS] = (float)(1.25 * mse);
    }
}

// ---------------------------------------------------------------------------
extern "C" void kernel_launch(void* const* d_in, const int* in_sizes, int n_in,
                              void* d_out, int out_size) {
    const float* inputs   = (const float*)d_in[0];   // [2048, 16384]
    const float* codebook = (const float*)d_in[1];   // [512, 16384]
    float* out = (float*)d_out;
    (void)in_sizes; (void)n_in; (void)out_size;

    static int smem_set = 0;
    if (!smem_set) {
        cudaFuncSetAttribute(k_mma, cudaFuncAttributeMaxDynamicSharedMemorySize, SMEM_TOTAL);
        smem_set = 1;
    }

    k_init<<<8, 256>>>();
    k_convert<<<2048, 256>>>(inputs, codebook);
    k_cbnorm<<<E_CODES, 256>>>(codebook);

    dim3 grid(B_ROWS / MT, E_CODES / NT, KSPLIT);    // (16, 4, 4) = 256 CTAs
    k_mma<<<grid, 256, SMEM_TOTAL>>>();

    k_argmin<<<B_ROWS / 8, 256>>>();
    k_zero_enc<<<256, 256>>>(out);
    k_gather<<<B_ROWS, 256>>>(inputs, codebook, out);
    k_scatter<<<(B_ROWS + 255) / 256, 256>>>(out);
    k_finalize<<<1, 512>>>(out);
}

// round 7
// speedup vs baseline: 5.9190x; 2.0696x over previous
#include <cuda_runtime.h>
#include <cuda_bf16.h>
#include <math.h>
#include <stdint.h>

// Problem shape (fixed by reference setup_inputs)
#define B_ROWS 2048
#define E_CODES 512
#define DIM     16384

// Output layout: tuple (loss, quantized_st, perplexity, encodings) flattened
#define OFF_LOSS 0ULL
#define OFF_Q    1ULL
#define OFF_PERP (1ULL + (unsigned long long)B_ROWS * DIM)
#define OFF_ENC  (OFF_PERP + 1ULL)

#define KSPLIT 4
#define TH 16.0f          // refine margin: ~40 sigma of bf16 score error
#define MAXCAND 32768

// ---------------------------------------------------------------------------
// Scratch (device globals: no allocations allowed)
__device__ __align__(16) __nv_bfloat16 g_Ah[(size_t)B_ROWS * DIM];
__device__ __align__(16) __nv_bfloat16 g_Bh[(size_t)E_CODES * DIM];
__device__ __align__(16) float         g_Dpart[(size_t)KSPLIT * B_ROWS * E_CODES]; // 16 MB
__device__ float               g_cb_norm[E_CODES];
__device__ unsigned long long  g_keys[B_ROWS];
__device__ uint32_t            g_cand[MAXCAND];
__device__ int                 g_ncand;
__device__ int                 g_counts[E_CODES];
__device__ double              g_loss_acc;

// ---------------------------------------------------------------------------
__device__ __forceinline__ uint32_t smem_u32(const void* p) {
    uint32_t a;
    asm("{ .reg .u64 t; cvta.to.shared.u64 t, %1; cvt.u32.u64 %0, t; }" : "=r"(a) : "l"(p));
    return a;
}
#define CP_ASYNC16(dst, src) \
    asm volatile("cp.async.cg.shared.global [%0], [%1], 16;" :: "r"(dst), "l"(src) : "memory")
#define CP_COMMIT() asm volatile("cp.async.commit_group;" ::: "memory")
#define CP_WAIT2()  asm volatile("cp.async.wait_group 2;" ::: "memory")

#define LDSM_X4(r, addr)                                                        \
    asm volatile("ldmatrix.sync.aligned.m8n8.x4.shared.b16 {%0,%1,%2,%3}, [%4];" \
        : "=r"((r)[0]), "=r"((r)[1]), "=r"((r)[2]), "=r"((r)[3]) : "r"(addr))

#define MMA_BF16(d, a0, a1, a2, a3, b0, b1)                                     \
    asm volatile("mma.sync.aligned.m16n8k16.row.col.f32.bf16.bf16.f32 "         \
        "{%0,%1,%2,%3}, {%4,%5,%6,%7}, {%8,%9}, {%0,%1,%2,%3};"                 \
        : "+f"((d)[0]), "+f"((d)[1]), "+f"((d)[2]), "+f"((d)[3])                \
        : "r"(a0), "r"(a1), "r"(a2), "r"(a3), "r"(b0), "r"(b1))

// SW128 swizzle (128-byte rows)
__device__ __forceinline__ uint32_t swz(uint32_t off) { return off ^ ((off >> 3) & 0x70); }

// ---------------------------------------------------------------------------
__global__ void k_init() {
    int t = blockIdx.x * blockDim.x + threadIdx.x;
    if (t < B_ROWS)  g_keys[t]  = 0xFFFFFFFFFFFFFFFFULL;
    if (t < E_CODES) g_counts[t] = 0;
    if (t == 0) { g_loss_acc = 0.0; g_ncand = 0; }
}

// ---------------------------------------------------------------------------
__device__ __forceinline__ float block_reduce_sum(float v) {
    __shared__ float red[32];
    int lane = threadIdx.x & 31;
    int w    = threadIdx.x >> 5;
    #pragma unroll
    for (int o = 16; o > 0; o >>= 1) v += __shfl_down_sync(0xffffffffu, v, o);
    if (lane == 0) red[w] = v;
    __syncthreads();
    if (w == 0) {
        v = (lane < ((int)blockDim.x >> 5)) ? red[lane] : 0.0f;
        #pragma unroll
        for (int o = 16; o > 0; o >>= 1) v += __shfl_down_sync(0xffffffffu, v, o);
    }
    return v;
}

// ---------------------------------------------------------------------------
// fp32 -> bf16 (round-to-nearest) for inputs and codebook
__global__ void k_convert(const float* __restrict__ A, const float* __restrict__ Cb) {
    const size_t nA = (size_t)B_ROWS * DIM / 4;
    const size_t nB = (size_t)E_CODES * DIM / 4;
    for (size_t i = blockIdx.x * (size_t)blockDim.x + threadIdx.x; i < nA + nB;
         i += (size_t)gridDim.x * blockDim.x) {
        float4 v = (i < nA) ? ((const float4*)A)[i] : ((const float4*)Cb)[i - nA];
        __nv_bfloat162 ha = __halves2bfloat162(__float2bfloat16(v.x), __float2bfloat16(v.y));
        __nv_bfloat162 hb = __halves2bfloat162(__float2bfloat16(v.z), __float2bfloat16(v.w));
        uint2 hp;
        hp.x = *(unsigned*)&ha; hp.y = *(unsigned*)&hb;
        if (i < nA) *(uint2*)(g_Ah + 4 * i) = hp;
        else        *(uint2*)(g_Bh + 4 * (i - nA)) = hp;
    }
}

// ---------------------------------------------------------------------------
// ||e||^2 per codebook row (fp32, from original codebook)
__global__ void k_cbnorm(const float* __restrict__ cb) {
    int e = blockIdx.x;
    const float4* row = (const float4*)(cb + (size_t)e * DIM);
    float s = 0.0f;
    for (int j = threadIdx.x; j < DIM / 4; j += blockDim.x) {
        float4 v = row[j];
        s += v.x * v.x + v.y * v.y + v.z * v.z + v.w * v.w;
    }
    float tot = block_reduce_sum(s);
    if (threadIdx.x == 0) g_cb_norm[e] = tot;
}

// ---------------------------------------------------------------------------
// bf16 GEMM via mma.sync (HMMA): dot(x_b, e_n) fp32 accum, single product.
// CTA tile 128x128, 8 warps (warp tile 32x64), KC=32, 4-stage cp.async.
// Stage layout: 128 rows x 128B; bytes [0,64) = A row, [64,128) = B row.
#define MT      128
#define NT      128
#define KC      32
#define NSTAGE  4
#define KSLICE  (DIM / KSPLIT)               // 4096
#define ITERS   (KSLICE / KC)                // 128
#define STAGE_B (128 * 128)                  // 16 KB
#define SMEM_TOTAL (NSTAGE * STAGE_B)        // 65536 B

__device__ __forceinline__ void load_stage(uint32_t sb, int st, int it, int m0, int n0,
                                           int kz, int tid) {
    const int kbase = kz + it * KC;
    #pragma unroll
    for (int j = 0; j < 4; j++) {
        int idx = tid + j * 256;             // 0..1023
        int r   = idx >> 3;                  // row 0..127
        int c   = idx & 7;                   // 16B chunk; c<4 -> A, c>=4 -> B
        const __nv_bfloat16* src;
        if (c < 4) src = g_Ah + (size_t)(m0 + r) * DIM + kbase + c * 8;
        else       src = g_Bh + (size_t)(n0 + r) * DIM + kbase + (c - 4) * 8;
        uint32_t dst = sb + st * STAGE_B + swz(r * 128 + c * 16);
        CP_ASYNC16(dst, src);
    }
}

__global__ void __launch_bounds__(256, 2) k_mma() {
    extern __shared__ __align__(128) char smem[];
    const uint32_t sb = smem_u32(smem);
    const int tid  = threadIdx.x;
    const int wid  = tid >> 5;
    const int lane = tid & 31;
    const int wm   = wid & 3;                // m block (32 rows)
    const int wn   = wid >> 2;               // n block (64 cols)
    const int m0   = blockIdx.x * MT;
    const int n0   = blockIdx.y * NT;
    const int kz   = blockIdx.z * KSLICE;

    float acc[2][8][4];
    #pragma unroll
    for (int mi = 0; mi < 2; mi++)
        #pragma unroll
        for (int nj = 0; nj < 8; nj++)
            #pragma unroll
            for (int q = 0; q < 4; q++) acc[mi][nj][q] = 0.0f;

    #pragma unroll
    for (int p = 0; p < NSTAGE - 1; p++) { load_stage(sb, p, p, m0, n0, kz, tid); CP_COMMIT(); }

    const uint32_t lrow = (lane & 15);
    const uint32_t lcol = (lane >> 4) * 16;

    for (int i = 0; i < ITERS; i++) {
        const int st = i & (NSTAGE - 1);
        CP_WAIT2();
        __syncthreads();
        if (i + NSTAGE - 1 < ITERS)
            load_stage(sb, (i + NSTAGE - 1) & (NSTAGE - 1), i + NSTAGE - 1, m0, n0, kz, tid);
        CP_COMMIT();

        const uint32_t s0 = sb + st * STAGE_B;
        #pragma unroll
        for (int ks = 0; ks < 2; ks++) {
            const uint32_t ko = ks * 32 + lcol;
            uint32_t a[2][4];
            #pragma unroll
            for (int mi = 0; mi < 2; mi++) {
                uint32_t ro = (wm * 32 + mi * 16 + lrow) * 128;
                LDSM_X4(a[mi], s0 + swz(ro + ko));
            }
            #pragma unroll
            for (int nq = 0; nq < 4; nq++) {
                uint32_t ro = (wn * 64 + nq * 16 + lrow) * 128 + 64;
                uint32_t b[4];
                LDSM_X4(b, s0 + swz(ro + ko));
                #pragma unroll
                for (int mi = 0; mi < 2; mi++) {
                    MMA_BF16(acc[mi][2 * nq],     a[mi][0], a[mi][1], a[mi][2], a[mi][3], b[0], b[2]);
                    MMA_BF16(acc[mi][2 * nq + 1], a[mi][0], a[mi][1], a[mi][2], a[mi][3], b[1], b[3]);
                }
            }
        }
    }

    // epilogue: write partial dots
    #pragma unroll
    for (int mi = 0; mi < 2; mi++) {
        #pragma unroll
        for (int nj = 0; nj < 8; nj++) {
            int row = m0 + wm * 32 + mi * 16 + (lane >> 2);
            int col = n0 + wn * 64 + nj * 8 + (lane & 3) * 2;
            float* d = &g_Dpart[((size_t)blockIdx.z * B_ROWS + row) * E_CODES + col];
            *(float2*)d = make_float2(acc[mi][nj][0], acc[mi][nj][1]);
            *(float2*)(d + 8 * E_CODES) = make_float2(acc[mi][nj][2], acc[mi][nj][3]);
        }
    }
}

// ---------------------------------------------------------------------------
// bf16 argmin per row + near-tie candidate extraction (one warp per row)
__global__ void k_argmin() {
    const int row  = blockIdx.x * 8 + (threadIdx.x >> 5);
    const int lane = threadIdx.x & 31;
    const size_t SL = (size_t)B_ROWS * E_CODES;
    const float* d = &g_Dpart[(size_t)row * E_CODES];
    float s[16];
    float m = 3.4e38f;
    #pragma unroll
    for (int j = 0; j < 16; j++) {
        int e = j * 32 + lane;
        float dot = 0.0f;
        #pragma unroll
        for (int z = 0; z < KSPLIT; z++) dot += d[z * SL + e];
        s[j] = g_cb_norm[e] - 2.0f * dot;
        m = fminf(m, s[j]);
    }
    #pragma unroll
    for (int o = 16; o > 0; o >>= 1) m = fminf(m, __shfl_xor_sync(0xffffffffu, m, o));

    // count candidates within TH of the min
    int cnt = 0;
    #pragma unroll
    for (int j = 0; j < 16; j++) cnt += (s[j] <= m + TH);
    #pragma unroll
    for (int o = 16; o > 0; o >>= 1) cnt += __shfl_xor_sync(0xffffffffu, cnt, o);

    if (cnt == 1) {
        // unique candidate: bf16 answer is provably the exact argmin
        int be = 0x7fffffff;
        #pragma unroll
        for (int j = 0; j < 16; j++) if (s[j] <= m + TH) be = j * 32 + lane;
        #pragma unroll
        for (int o = 16; o > 0; o >>= 1) be = min(be, __shfl_xor_sync(0xffffffffu, be, o));
        if (lane == 0) g_keys[row] = (unsigned long long)(unsigned)be;
    } else {
        // push all candidates for exact fp32 re-scoring
        #pragma unroll
        for (int j = 0; j < 16; j++) {
            if (s[j] <= m + TH) {
                int e = j * 32 + lane;
                int slot = atomicAdd(&g_ncand, 1);
                if (slot < MAXCAND) g_cand[slot] = ((unsigned)row << 9) | (unsigned)e;
            }
        }
    }
}

// ---------------------------------------------------------------------------
// exact fp32 re-score of near-tie candidates; atomicMin sortable keys
__global__ void k_refine(const float* __restrict__ A, const float* __restrict__ Cb) {
    const int n = g_ncand;
    for (int j = blockIdx.x; j < n && j < MAXCAND; j += gridDim.x) {
        uint32_t cd  = g_cand[j];
        int row  = cd >> 9;
        int code = cd & 511;
        const float4* x = (const float4*)(A  + (size_t)row  * DIM);
        const float4* e = (const float4*)(Cb + (size_t)code * DIM);
        float dot = 0.0f;
        for (int i = threadIdx.x; i < DIM / 4; i += blockDim.x) {
            float4 xv = x[i], ev = e[i];
            dot += xv.x * ev.x + xv.y * ev.y + xv.z * ev.z + xv.w * ev.w;
        }
        float tot = block_reduce_sum(dot);
        if (threadIdx.x == 0) {
            float sc = g_cb_norm[code] - 2.0f * tot;
            unsigned u = __float_as_uint(sc);
            u = (u & 0x80000000u) ? ~u : (u | 0x80000000u);
            unsigned long long key = ((unsigned long long)u << 32) | (unsigned)code;
            atomicMin(&g_keys[row], key);
        }
        __syncthreads();
    }
}

// ---------------------------------------------------------------------------
// zero the encodings region (poisoned by harness). Region is 8B-aligned only.
__global__ void k_zero_enc(float* __restrict__ out) {
    float2* p = (float2*)(out + OFF_ENC);
    int n2 = (B_ROWS * E_CODES) / 2;
    for (int i = blockIdx.x * blockDim.x + threadIdx.x; i < n2;
         i += gridDim.x * blockDim.x) {
        p[i] = make_float2(0.f, 0.f);
    }
}

// ---------------------------------------------------------------------------
// gather quantized rows + accumulate sum((q-x)^2). Output at out+1: scalar stores.
__global__ void k_gather(const float* __restrict__ A, const float* __restrict__ Cb,
                         float* __restrict__ out) {
    int b   = blockIdx.x;
    int idx = (int)(g_keys[b] & 0xFFFFFFFFu);
    const float4* q = (const float4*)(Cb + (size_t)idx * DIM);
    const float4* x = (const float4*)(A + (size_t)b * DIM);
    float*        o = out + OFF_Q + (size_t)b * DIM;
    float s = 0.0f;
    for (int j = threadIdx.x; j < DIM / 4; j += blockDim.x) {
        float4 qv = q[j];
        float4 xv = x[j];
        o[4 * j + 0] = qv.x;
        o[4 * j + 1] = qv.y;
        o[4 * j + 2] = qv.z;
        o[4 * j + 3] = qv.w;
        float d0 = qv.x - xv.x, d1 = qv.y - xv.y;
        float d2 = qv.z - xv.z, d3 = qv.w - xv.w;
        s += d0 * d0 + d1 * d1 + d2 * d2 + d3 * d3;
    }
    float tot = block_reduce_sum(s);
    if (threadIdx.x == 0) atomicAdd(&g_loss_acc, (double)tot);
}

// ---------------------------------------------------------------------------
__global__ void k_scatter(float* __restrict__ out) {
    int b = blockIdx.x * blockDim.x + threadIdx.x;
    if (b < B_ROWS) {
        int idx = (int)(g_keys[b] & 0xFFFFFFFFu);
        out[OFF_ENC + (size_t)b * E_CODES + idx] = 1.0f;
        atomicAdd(&g_counts[idx], 1);
    }
}

// ---------------------------------------------------------------------------
__global__ void k_finalize(float* __restrict__ out) {
    __shared__ float sh[512];
    int e = threadIdx.x;
    float p = (float)g_counts[e] / (float)B_ROWS;
    sh[e] = p * logf(p + 1e-10f);
    __syncthreads();
    for (int s = 256; s > 0; s >>= 1) {
        if (e < s) sh[e] += sh[e + s];
        __syncthreads();
    }
    if (e == 0) {
        out[OFF_PERP] = expf(-sh[0]);
        double mse = g_loss_acc / ((double)B_ROWS * (double)DIM);
        out[OFF_LOSS] = (float)(1.25 * mse);
    }
}

// ---------------------------------------------------------------------------
extern "C" void kernel_launch(void* const* d_in, const int* in_sizes, int n_in,
                              void* d_out, int out_size) {
    const float* inputs   = (const float*)d_in[0];   // [2048, 16384]
    const float* codebook = (const float*)d_in[1];   // [512, 16384]
    float* out = (float*)d_out;
    (void)in_sizes; (void)n_in; (void)out_size;

    static int smem_set = 0;
    if (!smem_set) {
        cudaFuncSetAttribute(k_mma, cudaFuncAttributeMaxDynamicSharedMemorySize, SMEM_TOTAL);
        smem_set = 1;
    }

    k_init<<<8, 256>>>();
    k_convert<<<2048, 256>>>(inputs, codebook);
    k_cbnorm<<<E_CODES, 256>>>(codebook);

    dim3 grid(B_ROWS / MT, E_CODES / NT, KSPLIT);    // (16, 4, 4) = 256 CTAs
    k_mma<<<grid, 256, SMEM_TOTAL>>>();

    k_argmin<<<B_ROWS / 8, 256>>>();
    k_refine<<<1024, 256>>>(inputs, codebook);
    k_zero_enc<<<256, 256>>>(out);
    k_gather<<<B_ROWS, 256>>>(inputs, codebook, out);
    k_scatter<<<(B_ROWS + 255) / 256, 256>>>(out);
    k_finalize<<<1, 512>>>(out);
}

// round 8
// speedup vs baseline: 6.3207x; 1.0679x over previous
#include <cuda_runtime.h>
#include <cuda_bf16.h>
#include <math.h>
#include <stdint.h>

// Problem shape (fixed by reference setup_inputs)
#define B_ROWS 2048
#define E_CODES 512
#define DIM     16384

// Output layout: tuple (loss, quantized_st, perplexity, encodings) flattened
#define OFF_LOSS 0ULL
#define OFF_Q    1ULL
#define OFF_PERP (1ULL + (unsigned long long)B_ROWS * DIM)
#define OFF_ENC  (OFF_PERP + 1ULL)

#define KSPLIT 4
#define TH 16.0f          // refine margin: ~40 sigma of bf16 score error
#define MAXCAND 32768

// ---------------------------------------------------------------------------
// Scratch (device globals: no allocations allowed)
__device__ __align__(16) __nv_bfloat16 g_Ah[(size_t)B_ROWS * DIM];
__device__ __align__(16) __nv_bfloat16 g_Bh[(size_t)E_CODES * DIM];
__device__ __align__(16) float         g_Dpart[(size_t)KSPLIT * B_ROWS * E_CODES]; // 16 MB
__device__ float               g_cb_norm[E_CODES];
__device__ unsigned long long  g_keys[B_ROWS];     // (sortable_score<<32)|idx
__device__ uint32_t            g_cand[MAXCAND];
__device__ int                 g_ncand;
__device__ int                 g_counts[E_CODES];
__device__ double              g_xnorm;

// ---------------------------------------------------------------------------
__device__ __forceinline__ uint32_t smem_u32(const void* p) {
    uint32_t a;
    asm("{ .reg .u64 t; cvta.to.shared.u64 t, %1; cvt.u32.u64 %0, t; }" : "=r"(a) : "l"(p));
    return a;
}
#define CP_ASYNC16(dst, src) \
    asm volatile("cp.async.cg.shared.global [%0], [%1], 16;" :: "r"(dst), "l"(src) : "memory")
#define CP_COMMIT() asm volatile("cp.async.commit_group;" ::: "memory")
#define CP_WAIT1()  asm volatile("cp.async.wait_group 1;" ::: "memory")

#define LDSM_X4(r, addr)                                                        \
    asm volatile("ldmatrix.sync.aligned.m8n8.x4.shared.b16 {%0,%1,%2,%3}, [%4];" \
        : "=r"((r)[0]), "=r"((r)[1]), "=r"((r)[2]), "=r"((r)[3]) : "r"(addr))

#define MMA_BF16(d, a0, a1, a2, a3, b0, b1)                                     \
    asm volatile("mma.sync.aligned.m16n8k16.row.col.f32.bf16.bf16.f32 "         \
        "{%0,%1,%2,%3}, {%4,%5,%6,%7}, {%8,%9}, {%0,%1,%2,%3};"                 \
        : "+f"((d)[0]), "+f"((d)[1]), "+f"((d)[2]), "+f"((d)[3])                \
        : "r"(a0), "r"(a1), "r"(a2), "r"(a3), "r"(b0), "r"(b1))

// SW128 swizzle (128-byte rows)
__device__ __forceinline__ uint32_t swz(uint32_t off) { return off ^ ((off >> 3) & 0x70); }

// sortable-float encode/decode (ascending order == float order)
__device__ __forceinline__ unsigned f2sort(float f) {
    unsigned u = __float_as_uint(f);
    return (u & 0x80000000u) ? ~u : (u | 0x80000000u);
}
__device__ __forceinline__ float sort2f(unsigned u) {
    return __uint_as_float((u & 0x80000000u) ? (u & 0x7fffffffu) : ~u);
}

// ---------------------------------------------------------------------------
__global__ void k_init() {
    int t = blockIdx.x * blockDim.x + threadIdx.x;
    if (t < B_ROWS)  g_keys[t]  = 0xFFFFFFFFFFFFFFFFULL;
    if (t < E_CODES) g_counts[t] = 0;
    if (t == 0) { g_xnorm = 0.0; g_ncand = 0; }
}

// ---------------------------------------------------------------------------
__device__ __forceinline__ float block_reduce_sum(float v) {
    __shared__ float red[32];
    int lane = threadIdx.x & 31;
    int w    = threadIdx.x >> 5;
    #pragma unroll
    for (int o = 16; o > 0; o >>= 1) v += __shfl_down_sync(0xffffffffu, v, o);
    if (lane == 0) red[w] = v;
    __syncthreads();
    if (w == 0) {
        v = (lane < ((int)blockDim.x >> 5)) ? red[lane] : 0.0f;
        #pragma unroll
        for (int o = 16; o > 0; o >>= 1) v += __shfl_down_sync(0xffffffffu, v, o);
    }
    return v;
}

// ---------------------------------------------------------------------------
// fp32 -> bf16 for inputs and codebook; also accumulate sum(x^2) over inputs
__global__ void k_convert(const float* __restrict__ A, const float* __restrict__ Cb) {
    const size_t nA = (size_t)B_ROWS * DIM / 4;
    const size_t nB = (size_t)E_CODES * DIM / 4;
    float xs = 0.0f;
    for (size_t i = blockIdx.x * (size_t)blockDim.x + threadIdx.x; i < nA + nB;
         i += (size_t)gridDim.x * blockDim.x) {
        float4 v = (i < nA) ? ((const float4*)A)[i] : ((const float4*)Cb)[i - nA];
        __nv_bfloat162 ha = __halves2bfloat162(__float2bfloat16(v.x), __float2bfloat16(v.y));
        __nv_bfloat162 hb = __halves2bfloat162(__float2bfloat16(v.z), __float2bfloat16(v.w));
        uint2 hp;
        hp.x = *(unsigned*)&ha; hp.y = *(unsigned*)&hb;
        if (i < nA) {
            *(uint2*)(g_Ah + 4 * i) = hp;
            xs += v.x * v.x + v.y * v.y + v.z * v.z + v.w * v.w;
        } else {
            *(uint2*)(g_Bh + 4 * (i - nA)) = hp;
        }
    }
    float tot = block_reduce_sum(xs);
    if (threadIdx.x == 0) atomicAdd(&g_xnorm, (double)tot);
}

// ---------------------------------------------------------------------------
// ||e||^2 per codebook row (fp32, from original codebook)
__global__ void k_cbnorm(const float* __restrict__ cb) {
    int e = blockIdx.x;
    const float4* row = (const float4*)(cb + (size_t)e * DIM);
    float s = 0.0f;
    for (int j = threadIdx.x; j < DIM / 4; j += blockDim.x) {
        float4 v = row[j];
        s += v.x * v.x + v.y * v.y + v.z * v.z + v.w * v.w;
    }
    float tot = block_reduce_sum(s);
    if (threadIdx.x == 0) g_cb_norm[e] = tot;
}

// ---------------------------------------------------------------------------
// bf16 GEMM via mma.sync (HMMA): dot(x_b, e_n) fp32 accum, single product.
// CTA tile 128x128, 8 warps (warp tile 32x64), KC=64, 3-stage cp.async.
// Stage: A tile 128 rows x 128B, B tile 128 rows x 128B (SW128-swizzled).
#define MT      128
#define NT      128
#define KC      64
#define NSTAGE  3
#define KSLICE  (DIM / KSPLIT)               // 4096
#define ITERS   (KSLICE / KC)                // 64
#define TILE_B  (128 * 128)                  // 16 KB
#define STAGE_B (2 * TILE_B)                 // 32 KB
#define SMEM_TOTAL (NSTAGE * STAGE_B)        // 98304 B

__device__ __forceinline__ void load_stage(uint32_t sb, int st, int it, int m0, int n0,
                                           int kz, int tid) {
    const int kbase = kz + it * KC;
    #pragma unroll
    for (int j = 0; j < 8; j++) {
        int idx = tid + j * 256;             // 0..2047
        int t   = idx >> 10;                 // 0:A  1:B
        int w   = idx & 1023;
        int r   = w >> 3;                    // row 0..127
        int c   = w & 7;                     // 16B chunk within 128B row
        const __nv_bfloat16* src;
        if (t == 0) src = g_Ah + (size_t)(m0 + r) * DIM + kbase + c * 8;
        else        src = g_Bh + (size_t)(n0 + r) * DIM + kbase + c * 8;
        uint32_t dst = sb + st * STAGE_B + t * TILE_B + swz(r * 128 + c * 16);
        CP_ASYNC16(dst, src);
    }
}

__global__ void __launch_bounds__(256, 2) k_mma() {
    extern __shared__ __align__(128) char smem[];
    const uint32_t sb = smem_u32(smem);
    const int tid  = threadIdx.x;
    const int wid  = tid >> 5;
    const int lane = tid & 31;
    const int wm   = wid & 3;                // m block (32 rows)
    const int wn   = wid >> 2;               // n block (64 cols)
    const int m0   = blockIdx.x * MT;
    const int n0   = blockIdx.y * NT;
    const int kz   = blockIdx.z * KSLICE;

    float acc[2][8][4];
    #pragma unroll
    for (int mi = 0; mi < 2; mi++)
        #pragma unroll
        for (int nj = 0; nj < 8; nj++)
            #pragma unroll
            for (int q = 0; q < 4; q++) acc[mi][nj][q] = 0.0f;

    #pragma unroll
    for (int p = 0; p < NSTAGE - 1; p++) { load_stage(sb, p, p, m0, n0, kz, tid); CP_COMMIT(); }

    const uint32_t lrow = (lane & 15);
    const uint32_t lcol = (lane >> 4) * 16;

    for (int i = 0; i < ITERS; i++) {
        const int st = i % NSTAGE;
        CP_WAIT1();
        __syncthreads();
        if (i + NSTAGE - 1 < ITERS)
            load_stage(sb, (i + NSTAGE - 1) % NSTAGE, i + NSTAGE - 1, m0, n0, kz, tid);
        CP_COMMIT();

        const uint32_t s0 = sb + st * STAGE_B;
        #pragma unroll
        for (int ks = 0; ks < 4; ks++) {
            const uint32_t ko = ks * 32 + lcol;
            uint32_t a[2][4];
            #pragma unroll
            for (int mi = 0; mi < 2; mi++) {
                uint32_t ro = (wm * 32 + mi * 16 + lrow) * 128;
                LDSM_X4(a[mi], s0 + swz(ro + ko));
            }
            #pragma unroll
            for (int nq = 0; nq < 4; nq++) {
                uint32_t ro = (wn * 64 + nq * 16 + lrow) * 128;
                uint32_t b[4];
                LDSM_X4(b, s0 + TILE_B + swz(ro + ko));
                #pragma unroll
                for (int mi = 0; mi < 2; mi++) {
                    MMA_BF16(acc[mi][2 * nq],     a[mi][0], a[mi][1], a[mi][2], a[mi][3], b[0], b[2]);
                    MMA_BF16(acc[mi][2 * nq + 1], a[mi][0], a[mi][1], a[mi][2], a[mi][3], b[1], b[3]);
                }
            }
        }
    }

    // epilogue: write partial dots
    #pragma unroll
    for (int mi = 0; mi < 2; mi++) {
        #pragma unroll
        for (int nj = 0; nj < 8; nj++) {
            int row = m0 + wm * 32 + mi * 16 + (lane >> 2);
            int col = n0 + wn * 64 + nj * 8 + (lane & 3) * 2;
            float* d = &g_Dpart[((size_t)blockIdx.z * B_ROWS + row) * E_CODES + col];
            *(float2*)d = make_float2(acc[mi][nj][0], acc[mi][nj][1]);
            *(float2*)(d + 8 * E_CODES) = make_float2(acc[mi][nj][2], acc[mi][nj][3]);
        }
    }
}

// ---------------------------------------------------------------------------
// bf16 argmin per row + near-tie candidate extraction (one warp per row)
__global__ void k_argmin() {
    const int row  = blockIdx.x * 8 + (threadIdx.x >> 5);
    const int lane = threadIdx.x & 31;
    const size_t SL = (size_t)B_ROWS * E_CODES;
    const float* d = &g_Dpart[(size_t)row * E_CODES];
    float s[16];
    float m = 3.4e38f;
    #pragma unroll
    for (int j = 0; j < 16; j++) {
        int e = j * 32 + lane;
        float dot = 0.0f;
        #pragma unroll
        for (int z = 0; z < KSPLIT; z++) dot += d[z * SL + e];
        s[j] = g_cb_norm[e] - 2.0f * dot;
        m = fminf(m, s[j]);
    }
    #pragma unroll
    for (int o = 16; o > 0; o >>= 1) m = fminf(m, __shfl_xor_sync(0xffffffffu, m, o));

    int cnt = 0;
    #pragma unroll
    for (int j = 0; j < 16; j++) cnt += (s[j] <= m + TH);
    #pragma unroll
    for (int o = 16; o > 0; o >>= 1) cnt += __shfl_xor_sync(0xffffffffu, cnt, o);

    if (cnt == 1) {
        // unique candidate: bf16 answer is provably the exact argmin
        int be = 0x7fffffff;
        #pragma unroll
        for (int j = 0; j < 16; j++) if (s[j] <= m + TH) be = j * 32 + lane;
        #pragma unroll
        for (int o = 16; o > 0; o >>= 1) be = min(be, __shfl_xor_sync(0xffffffffu, be, o));
        if (lane == 0)
            g_keys[row] = ((unsigned long long)f2sort(m) << 32) | (unsigned)be;
    } else {
        #pragma unroll
        for (int j = 0; j < 16; j++) {
            if (s[j] <= m + TH) {
                int e = j * 32 + lane;
                int slot = atomicAdd(&g_ncand, 1);
                if (slot < MAXCAND) g_cand[slot] = ((unsigned)row << 9) | (unsigned)e;
            }
        }
    }
}

// ---------------------------------------------------------------------------
// exact fp32 re-score of near-tie candidates; atomicMin sortable keys
__global__ void k_refine(const float* __restrict__ A, const float* __restrict__ Cb) {
    const int n = g_ncand;
    for (int j = blockIdx.x; j < n && j < MAXCAND; j += gridDim.x) {
        uint32_t cd  = g_cand[j];
        int row  = cd >> 9;
        int code = cd & 511;
        const float4* x = (const float4*)(A  + (size_t)row  * DIM);
        const float4* e = (const float4*)(Cb + (size_t)code * DIM);
        float dot = 0.0f;
        for (int i = threadIdx.x; i < DIM / 4; i += blockDim.x) {
            float4 xv = x[i], ev = e[i];
            dot += xv.x * ev.x + xv.y * ev.y + xv.z * ev.z + xv.w * ev.w;
        }
        float tot = block_reduce_sum(dot);
        if (threadIdx.x == 0) {
            float sc = g_cb_norm[code] - 2.0f * tot;
            unsigned long long key = ((unsigned long long)f2sort(sc) << 32) | (unsigned)code;
            atomicMin(&g_keys[row], key);
        }
        __syncthreads();
    }
}

// ---------------------------------------------------------------------------
// per row b: zero+set one-hot enc row, histogram count, gather codebook row.
// Output q-region starts at out+1 (4B aligned) -> scalar stores; enc is 8B aligned.
__global__ void k_gather(const float* __restrict__ Cb, float* __restrict__ out) {
    int b   = blockIdx.x;
    int idx = (int)(g_keys[b] & 0xFFFFFFFFu);

    // encodings row: zero 512 floats with float2, then set one-hot
    float2* enc = (float2*)(out + OFF_ENC + (size_t)b * E_CODES);
    if (threadIdx.x < 256) enc[threadIdx.x] = make_float2(0.f, 0.f);
    __syncthreads();
    if (threadIdx.x == 0) {
        out[OFF_ENC + (size_t)b * E_CODES + idx] = 1.0f;
        atomicAdd(&g_counts[idx], 1);
    }

    const float4* q = (const float4*)(Cb + (size_t)idx * DIM);
    float*        o = out + OFF_Q + (size_t)b * DIM;
    for (int j = threadIdx.x; j < DIM / 4; j += blockDim.x) {
        float4 qv = q[j];
        o[4 * j + 0] = qv.x;
        o[4 * j + 1] = qv.y;
        o[4 * j + 2] = qv.z;
        o[4 * j + 3] = qv.w;
    }
}

// ---------------------------------------------------------------------------
// loss from Sum(best scores) + Sum(x^2); perplexity from counts
__global__ void k_finalize(float* __restrict__ out) {
    __shared__ double sh[512];
    int t = threadIdx.x;

    double s = 0.0;
    for (int r = t; r < B_ROWS; r += 512)
        s += (double)sort2f((unsigned)(g_keys[r] >> 32));
    sh[t] = s;
    __syncthreads();
    for (int k = 256; k > 0; k >>= 1) {
        if (t < k) sh[t] += sh[t + k];
        __syncthreads();
    }
    double score_sum = sh[0];
    __syncthreads();

    float p = (float)g_counts[t] / (float)B_ROWS;
    sh[t] = (double)(p * logf(p + 1e-10f));
    __syncthreads();
    for (int k = 256; k > 0; k >>= 1) {
        if (t < k) sh[t] += sh[t + k];
        __syncthreads();
    }
    if (t == 0) {
        out[OFF_PERP] = expf(-(float)sh[0]);
        double mse = (score_sum + g_xnorm) / ((double)B_ROWS * (double)DIM);
        out[OFF_LOSS] = (float)(1.25 * mse);
    }
}

// ---------------------------------------------------------------------------
extern "C" void kernel_launch(void* const* d_in, const int* in_sizes, int n_in,
                              void* d_out, int out_size) {
    const float* inputs   = (const float*)d_in[0];   // [2048, 16384]
    const float* codebook = (const float*)d_in[1];   // [512, 16384]
    float* out = (float*)d_out;
    (void)in_sizes; (void)n_in; (void)out_size;

    static int smem_set = 0;
    if (!smem_set) {
        cudaFuncSetAttribute(k_mma, cudaFuncAttributeMaxDynamicSharedMemorySize, SMEM_TOTAL);
        smem_set = 1;
    }

    k_init<<<8, 256>>>();
    k_convert<<<2048, 256>>>(inputs, codebook);
    k_cbnorm<<<E_CODES, 256>>>(codebook);

    dim3 grid(B_ROWS / MT, E_CODES / NT, KSPLIT);    // (16, 4, 4) = 256 CTAs
    k_mma<<<grid, 256, SMEM_TOTAL>>>();

    k_argmin<<<B_ROWS / 8, 256>>>();
    k_refine<<<1024, 256>>>(inputs, codebook);
    k_gather<<<B_ROWS, 256>>>(codebook, out);
    k_finalize<<<1, 512>>>(out);
}

// round 9
// speedup vs baseline: 6.8991x; 1.0915x over previous
#include <cuda_runtime.h>
#include <cuda_bf16.h>
#include <math.h>
#include <stdint.h>

// Problem shape (fixed by reference setup_inputs)
#define B_ROWS 2048
#define E_CODES 512
#define DIM     16384

// Output layout: tuple (loss, quantized_st, perplexity, encodings) flattened
#define OFF_LOSS 0ULL
#define OFF_Q    1ULL
#define OFF_PERP (1ULL + (unsigned long long)B_ROWS * DIM)
#define OFF_ENC  (OFF_PERP + 1ULL)

#define KSPLIT 4
#define TH 16.0f          // refine margin: ~40 sigma of bf16 score error
#define MAXCAND 32768

// ---------------------------------------------------------------------------
// Scratch (device globals: no allocations allowed)
__device__ __align__(16) __nv_bfloat16 g_Ah[(size_t)B_ROWS * DIM];
__device__ __align__(16) __nv_bfloat16 g_Bh[(size_t)E_CODES * DIM];
__device__ __align__(16) float         g_Dpart[(size_t)KSPLIT * B_ROWS * E_CODES]; // 16 MB
__device__ float               g_cb_norm[E_CODES];
__device__ unsigned long long  g_keys[B_ROWS];     // (sortable_score<<32)|idx
__device__ uint32_t            g_cand[MAXCAND];
__device__ int                 g_ncand;
__device__ int                 g_counts[E_CODES];
__device__ double              g_xnorm;

// ---------------------------------------------------------------------------
__device__ __forceinline__ uint32_t smem_u32(const void* p) {
    uint32_t a;
    asm("{ .reg .u64 t; cvta.to.shared.u64 t, %1; cvt.u32.u64 %0, t; }" : "=r"(a) : "l"(p));
    return a;
}
#define CP_ASYNC16(dst, src) \
    asm volatile("cp.async.cg.shared.global [%0], [%1], 16;" :: "r"(dst), "l"(src) : "memory")
#define CP_COMMIT() asm volatile("cp.async.commit_group;" ::: "memory")
#define CP_WAIT1()  asm volatile("cp.async.wait_group 1;" ::: "memory")

#define LDSM_X4(r, addr)                                                        \
    asm volatile("ldmatrix.sync.aligned.m8n8.x4.shared.b16 {%0,%1,%2,%3}, [%4];" \
        : "=r"((r)[0]), "=r"((r)[1]), "=r"((r)[2]), "=r"((r)[3]) : "r"(addr))

#define MMA_BF16(d, a0, a1, a2, a3, b0, b1)                                     \
    asm volatile("mma.sync.aligned.m16n8k16.row.col.f32.bf16.bf16.f32 "         \
        "{%0,%1,%2,%3}, {%4,%5,%6,%7}, {%8,%9}, {%0,%1,%2,%3};"                 \
        : "+f"((d)[0]), "+f"((d)[1]), "+f"((d)[2]), "+f"((d)[3])                \
        : "r"(a0), "r"(a1), "r"(a2), "r"(a3), "r"(b0), "r"(b1))

// SW128 swizzle (128-byte rows)
__device__ __forceinline__ uint32_t swz(uint32_t off) { return off ^ ((off >> 3) & 0x70); }

// sortable-float encode/decode (ascending order == float order)
__device__ __forceinline__ unsigned f2sort(float f) {
    unsigned u = __float_as_uint(f);
    return (u & 0x80000000u) ? ~u : (u | 0x80000000u);
}
__device__ __forceinline__ float sort2f(unsigned u) {
    return __uint_as_float((u & 0x80000000u) ? (u & 0x7fffffffu) : ~u);
}
__device__ __forceinline__ unsigned pack_bf2(float x, float y) {
    __nv_bfloat162 h = __halves2bfloat162(__float2bfloat16(x), __float2bfloat16(y));
    return *(unsigned*)&h;
}

// ---------------------------------------------------------------------------
__global__ void k_init() {
    int t = blockIdx.x * blockDim.x + threadIdx.x;
    if (t < B_ROWS)  g_keys[t]  = 0xFFFFFFFFFFFFFFFFULL;
    if (t < E_CODES) g_counts[t] = 0;
    if (t == 0) { g_xnorm = 0.0; g_ncand = 0; }
}

// ---------------------------------------------------------------------------
__device__ __forceinline__ float block_reduce_sum(float v) {
    __shared__ float red[32];
    int lane = threadIdx.x & 31;
    int w    = threadIdx.x >> 5;
    #pragma unroll
    for (int o = 16; o > 0; o >>= 1) v += __shfl_down_sync(0xffffffffu, v, o);
    if (lane == 0) red[w] = v;
    __syncthreads();
    if (w == 0) {
        v = (lane < ((int)blockDim.x >> 5)) ? red[lane] : 0.0f;
        #pragma unroll
        for (int o = 16; o > 0; o >>= 1) v += __shfl_down_sync(0xffffffffu, v, o);
    }
    return v;
}

// ---------------------------------------------------------------------------
// fp32 -> bf16 for inputs and codebook (8 floats/thread, 16B stores);
// accumulate sum(x^2) over inputs.
__global__ void k_convert(const float* __restrict__ A, const float* __restrict__ Cb) {
    const size_t nA8 = (size_t)B_ROWS * DIM / 8;
    const size_t nB8 = (size_t)E_CODES * DIM / 8;
    const size_t gid = blockIdx.x * (size_t)blockDim.x + threadIdx.x;
    const size_t stride = (size_t)gridDim.x * blockDim.x;
    float xs = 0.0f;
    for (size_t j = gid; j < nA8; j += stride) {
        const float4* pa = (const float4*)A + 2 * j;
        float4 v0 = pa[0], v1 = pa[1];
        uint4 hp;
        hp.x = pack_bf2(v0.x, v0.y); hp.y = pack_bf2(v0.z, v0.w);
        hp.z = pack_bf2(v1.x, v1.y); hp.w = pack_bf2(v1.z, v1.w);
        *(uint4*)(g_Ah + 8 * j) = hp;
        xs += v0.x * v0.x + v0.y * v0.y + v0.z * v0.z + v0.w * v0.w
            + v1.x * v1.x + v1.y * v1.y + v1.z * v1.z + v1.w * v1.w;
    }
    for (size_t j = gid; j < nB8; j += stride) {
        const float4* pb = (const float4*)Cb + 2 * j;
        float4 v0 = pb[0], v1 = pb[1];
        uint4 hp;
        hp.x = pack_bf2(v0.x, v0.y); hp.y = pack_bf2(v0.z, v0.w);
        hp.z = pack_bf2(v1.x, v1.y); hp.w = pack_bf2(v1.z, v1.w);
        *(uint4*)(g_Bh + 8 * j) = hp;
    }
    float tot = block_reduce_sum(xs);
    if (threadIdx.x == 0) atomicAdd(&g_xnorm, (double)tot);
}

// ---------------------------------------------------------------------------
// ||e||^2 per codebook row (fp32, from original codebook; deterministic tree)
__global__ void k_cbnorm(const float* __restrict__ cb) {
    int e = blockIdx.x;
    const float4* row = (const float4*)(cb + (size_t)e * DIM);
    float s = 0.0f;
    for (int j = threadIdx.x; j < DIM / 4; j += blockDim.x) {
        float4 v = row[j];
        s += v.x * v.x + v.y * v.y + v.z * v.z + v.w * v.w;
    }
    float tot = block_reduce_sum(s);
    if (threadIdx.x == 0) g_cb_norm[e] = tot;
}

// ---------------------------------------------------------------------------
// bf16 GEMM via mma.sync (HMMA): dot(x_b, e_n) fp32 accum, single product.
// CTA tile 128x128, 8 warps (warp tile 32x64), KC=64, 3-stage cp.async.
#define MT      128
#define NT      128
#define KC      64
#define NSTAGE  3
#define KSLICE  (DIM / KSPLIT)               // 4096
#define ITERS   (KSLICE / KC)                // 64
#define TILE_B  (128 * 128)                  // 16 KB
#define STAGE_B (2 * TILE_B)                 // 32 KB
#define SMEM_TOTAL (NSTAGE * STAGE_B)        // 98304 B

__device__ __forceinline__ void load_stage(uint32_t sb, int st, int it, int m0, int n0,
                                           int kz, int tid) {
    const int kbase = kz + it * KC;
    #pragma unroll
    for (int j = 0; j < 8; j++) {
        int idx = tid + j * 256;             // 0..2047
        int t   = idx >> 10;                 // 0:A  1:B
        int w   = idx & 1023;
        int r   = w >> 3;                    // row 0..127
        int c   = w & 7;                     // 16B chunk within 128B row
        const __nv_bfloat16* src;
        if (t == 0) src = g_Ah + (size_t)(m0 + r) * DIM + kbase + c * 8;
        else        src = g_Bh + (size_t)(n0 + r) * DIM + kbase + c * 8;
        uint32_t dst = sb + st * STAGE_B + t * TILE_B + swz(r * 128 + c * 16);
        CP_ASYNC16(dst, src);
    }
}

__global__ void __launch_bounds__(256, 2) k_mma() {
    extern __shared__ __align__(128) char smem[];
    const uint32_t sb = smem_u32(smem);
    const int tid  = threadIdx.x;
    const int wid  = tid >> 5;
    const int lane = tid & 31;
    const int wm   = wid & 3;                // m block (32 rows)
    const int wn   = wid >> 2;               // n block (64 cols)
    const int m0   = blockIdx.x * MT;
    const int n0   = blockIdx.y * NT;
    const int kz   = blockIdx.z * KSLICE;

    float acc[2][8][4];
    #pragma unroll
    for (int mi = 0; mi < 2; mi++)
        #pragma unroll
        for (int nj = 0; nj < 8; nj++)
            #pragma unroll
            for (int q = 0; q < 4; q++) acc[mi][nj][q] = 0.0f;

    #pragma unroll
    for (int p = 0; p < NSTAGE - 1; p++) { load_stage(sb, p, p, m0, n0, kz, tid); CP_COMMIT(); }

    const uint32_t lrow = (lane & 15);
    const uint32_t lcol = (lane >> 4) * 16;

    for (int i = 0; i < ITERS; i++) {
        const int st = i % NSTAGE;
        CP_WAIT1();
        __syncthreads();
        if (i + NSTAGE - 1 < ITERS)
            load_stage(sb, (i + NSTAGE - 1) % NSTAGE, i + NSTAGE - 1, m0, n0, kz, tid);
        CP_COMMIT();

        const uint32_t s0 = sb + st * STAGE_B;
        #pragma unroll
        for (int ks = 0; ks < 4; ks++) {
            const uint32_t ko = ks * 32 + lcol;
            // issue ALL fragment loads first, then the 16 MMAs (one exposed
            // LDSM latency per ks instead of four)
            uint32_t a[2][4], b[4][4];
            #pragma unroll
            for (int mi = 0; mi < 2; mi++) {
                uint32_t ro = (wm * 32 + mi * 16 + lrow) * 128;
                LDSM_X4(a[mi], s0 + swz(ro + ko));
            }
            #pragma unroll
            for (int nq = 0; nq < 4; nq++) {
                uint32_t ro = (wn * 64 + nq * 16 + lrow) * 128;
                LDSM_X4(b[nq], s0 + TILE_B + swz(ro + ko));
            }
            #pragma unroll
            for (int nq = 0; nq < 4; nq++)
                #pragma unroll
                for (int mi = 0; mi < 2; mi++) {
                    MMA_BF16(acc[mi][2 * nq],     a[mi][0], a[mi][1], a[mi][2], a[mi][3],
                             b[nq][0], b[nq][2]);
                    MMA_BF16(acc[mi][2 * nq + 1], a[mi][0], a[mi][1], a[mi][2], a[mi][3],
                             b[nq][1], b[nq][3]);
                }
        }
    }

    // epilogue: write partial dots
    #pragma unroll
    for (int mi = 0; mi < 2; mi++) {
        #pragma unroll
        for (int nj = 0; nj < 8; nj++) {
            int row = m0 + wm * 32 + mi * 16 + (lane >> 2);
            int col = n0 + wn * 64 + nj * 8 + (lane & 3) * 2;
            float* d = &g_Dpart[((size_t)blockIdx.z * B_ROWS + row) * E_CODES + col];
            *(float2*)d = make_float2(acc[mi][nj][0], acc[mi][nj][1]);
            *(float2*)(d + 8 * E_CODES) = make_float2(acc[mi][nj][2], acc[mi][nj][3]);
        }
    }
}

// ---------------------------------------------------------------------------
// bf16 argmin per row + near-tie candidate extraction (one warp per row)
__global__ void k_argmin() {
    const int row  = blockIdx.x * 8 + (threadIdx.x >> 5);
    const int lane = threadIdx.x & 31;
    const size_t SL = (size_t)B_ROWS * E_CODES;
    const float* d = &g_Dpart[(size_t)row * E_CODES];
    float s[16];
    float m = 3.4e38f;
    #pragma unroll
    for (int j = 0; j < 16; j++) {
        int e = j * 32 + lane;
        float dot = 0.0f;
        #pragma unroll
        for (int z = 0; z < KSPLIT; z++) dot += d[z * SL + e];
        s[j] = g_cb_norm[e] - 2.0f * dot;
        m = fminf(m, s[j]);
    }
    #pragma unroll
    for (int o = 16; o > 0; o >>= 1) m = fminf(m, __shfl_xor_sync(0xffffffffu, m, o));

    int cnt = 0;
    #pragma unroll
    for (int j = 0; j < 16; j++) cnt += (s[j] <= m + TH);
    #pragma unroll
    for (int o = 16; o > 0; o >>= 1) cnt += __shfl_xor_sync(0xffffffffu, cnt, o);

    if (cnt == 1) {
        int be = 0x7fffffff;
        #pragma unroll
        for (int j = 0; j < 16; j++) if (s[j] <= m + TH) be = j * 32 + lane;
        #pragma unroll
        for (int o = 16; o > 0; o >>= 1) be = min(be, __shfl_xor_sync(0xffffffffu, be, o));
        if (lane == 0)
            g_keys[row] = ((unsigned long long)f2sort(m) << 32) | (unsigned)be;
    } else {
        #pragma unroll
        for (int j = 0; j < 16; j++) {
            if (s[j] <= m + TH) {
                int e = j * 32 + lane;
                int slot = atomicAdd(&g_ncand, 1);
                if (slot < MAXCAND) g_cand[slot] = ((unsigned)row << 9) | (unsigned)e;
            }
        }
    }
}

// ---------------------------------------------------------------------------
// exact fp32 re-score of near-tie candidates; atomicMin sortable keys
__global__ void k_refine(const float* __restrict__ A, const float* __restrict__ Cb) {
    const int n = g_ncand;
    for (int j = blockIdx.x; j < n && j < MAXCAND; j += gridDim.x) {
        uint32_t cd  = g_cand[j];
        int row  = cd >> 9;
        int code = cd & 511;
        const float4* x = (const float4*)(A  + (size_t)row  * DIM);
        const float4* e = (const float4*)(Cb + (size_t)code * DIM);
        float dot = 0.0f;
        for (int i = threadIdx.x; i < DIM / 4; i += blockDim.x) {
            float4 xv = x[i], ev = e[i];
            dot += xv.x * ev.x + xv.y * ev.y + xv.z * ev.z + xv.w * ev.w;
        }
        float tot = block_reduce_sum(dot);
        if (threadIdx.x == 0) {
            float sc = g_cb_norm[code] - 2.0f * tot;
            unsigned long long key = ((unsigned long long)f2sort(sc) << 32) | (unsigned)code;
            atomicMin(&g_keys[row], key);
        }
        __syncthreads();
    }
}

// ---------------------------------------------------------------------------
// per row b: one-hot enc row + histogram + gather codebook row (vectorized).
// q-region starts at out+1 (element offset ≡1 mod 4): 3-elem prefix, shifted
// float4 bulk, 1-elem tail.
__global__ void k_gather(const float* __restrict__ Cb, float* __restrict__ out) {
    int b   = blockIdx.x;
    int idx = (int)(g_keys[b] & 0xFFFFFFFFu);

    // encodings row: zero 512 floats with float2, then set one-hot
    float2* enc = (float2*)(out + OFF_ENC + (size_t)b * E_CODES);
    if (threadIdx.x < 256) enc[threadIdx.x] = make_float2(0.f, 0.f);
    __syncthreads();
    if (threadIdx.x == 0) {
        out[OFF_ENC + (size_t)b * E_CODES + idx] = 1.0f;
        atomicAdd(&g_counts[idx], 1);
    }

    const float*  q  = Cb + (size_t)idx * DIM;
    const float4* q4 = (const float4*)q;
    float* o = out + OFF_Q + (size_t)b * DIM;
    if (threadIdx.x < 3) o[threadIdx.x] = q[threadIdx.x];        // prefix 0..2
    if (threadIdx.x == 3) o[DIM - 1] = q[DIM - 1];               // tail 16383
    float4* o4 = (float4*)(o + 3);                               // 16B aligned
    for (int t = threadIdx.x; t < (DIM - 4) / 4; t += blockDim.x) {
        float4 s0 = q4[t];
        float4 s1 = q4[t + 1];
        o4[t] = make_float4(s0.w, s1.x, s1.y, s1.z);
    }
}

// ---------------------------------------------------------------------------
// loss from Sum(best scores) + Sum(x^2); perplexity from counts
__global__ void k_finalize(float* __restrict__ out) {
    __shared__ double sh[512];
    int t = threadIdx.x;

    double s = 0.0;
    for (int r = t; r < B_ROWS; r += 512)
        s += (double)sort2f((unsigned)(g_keys[r] >> 32));
    sh[t] = s;
    __syncthreads();
    for (int k = 256; k > 0; k >>= 1) {
        if (t < k) sh[t] += sh[t + k];
        __syncthreads();
    }
    double score_sum = sh[0];
    __syncthreads();

    float p = (float)g_counts[t] / (float)B_ROWS;
    sh[t] = (double)(p * logf(p + 1e-10f));
    __syncthreads();
    for (int k = 256; k > 0; k >>= 1) {
        if (t < k) sh[t] += sh[t + k];
        __syncthreads();
    }
    if (t == 0) {
        out[OFF_PERP] = expf(-(float)sh[0]);
        double mse = (score_sum + g_xnorm) / ((double)B_ROWS * (double)DIM);
        out[OFF_LOSS] = (float)(1.25 * mse);
    }
}

// ---------------------------------------------------------------------------
extern "C" void kernel_launch(void* const* d_in, const int* in_sizes, int n_in,
                              void* d_out, int out_size) {
    const float* inputs   = (const float*)d_in[0];   // [2048, 16384]
    const float* codebook = (const float*)d_in[1];   // [512, 16384]
    float* out = (float*)d_out;
    (void)in_sizes; (void)n_in; (void)out_size;

    static int smem_set = 0;
    if (!smem_set) {
        cudaFuncSetAttribute(k_mma, cudaFuncAttributeMaxDynamicSharedMemorySize, SMEM_TOTAL);
        smem_set = 1;
    }

    k_init<<<8, 256>>>();
    k_convert<<<2048, 256>>>(inputs, codebook);
    k_cbnorm<<<E_CODES, 256>>>(codebook);

    dim3 grid(B_ROWS / MT, E_CODES / NT, KSPLIT);    // (16, 4, 4) = 256 CTAs
    k_mma<<<grid, 256, SMEM_TOTAL>>>();

    k_argmin<<<B_ROWS / 8, 256>>>();
    k_refine<<<1024, 256>>>(inputs, codebook);
    k_gather<<<B_ROWS, 256>>>(codebook, out);
    k_finalize<<<1, 512>>>(out);
}

// round 10
// speedup vs baseline: 6.9055x; 1.0009x over previous
#include <cuda_runtime.h>
#include <cuda_bf16.h>
#include <math.h>
#include <stdint.h>

// Problem shape (fixed by reference setup_inputs)
#define B_ROWS 2048
#define E_CODES 512
#define DIM     16384

// Output layout: tuple (loss, quantized_st, perplexity, encodings) flattened
#define OFF_LOSS 0ULL
#define OFF_Q    1ULL
#define OFF_PERP (1ULL + (unsigned long long)B_ROWS * DIM)
#define OFF_ENC  (OFF_PERP + 1ULL)

#define KSPLIT 4
#define TH 16.0f          // refine margin: ~40 sigma of bf16 score error
#define MAXCAND 32768

// ---------------------------------------------------------------------------
// Scratch (device globals: no allocations allowed)
__device__ __align__(16) __nv_bfloat16 g_Ah[(size_t)B_ROWS * DIM];
__device__ __align__(16) __nv_bfloat16 g_Bh[(size_t)E_CODES * DIM];
__device__ __align__(16) float         g_Dpart[(size_t)KSPLIT * B_ROWS * E_CODES]; // 16 MB
__device__ float               g_cb_norm[E_CODES];
__device__ unsigned long long  g_keys[B_ROWS];     // (sortable_score<<32)|idx
__device__ uint32_t            g_cand[MAXCAND];
__device__ int                 g_ncand;
__device__ int                 g_counts[E_CODES];
__device__ double              g_xnorm;

// ---------------------------------------------------------------------------
__device__ __forceinline__ uint32_t smem_u32(const void* p) {
    uint32_t a;
    asm("{ .reg .u64 t; cvta.to.shared.u64 t, %1; cvt.u32.u64 %0, t; }" : "=r"(a) : "l"(p));
    return a;
}
#define CP_ASYNC16(dst, src) \
    asm volatile("cp.async.cg.shared.global [%0], [%1], 16;" :: "r"(dst), "l"(src) : "memory")
#define CP_COMMIT() asm volatile("cp.async.commit_group;" ::: "memory")
#define CP_WAIT1()  asm volatile("cp.async.wait_group 1;" ::: "memory")

#define LDSM_X4(r, addr)                                                        \
    asm volatile("ldmatrix.sync.aligned.m8n8.x4.shared.b16 {%0,%1,%2,%3}, [%4];" \
        : "=r"((r)[0]), "=r"((r)[1]), "=r"((r)[2]), "=r"((r)[3]) : "r"(addr))

#define MMA_BF16(d, a0, a1, a2, a3, b0, b1)                                     \
    asm volatile("mma.sync.aligned.m16n8k16.row.col.f32.bf16.bf16.f32 "         \
        "{%0,%1,%2,%3}, {%4,%5,%6,%7}, {%8,%9}, {%0,%1,%2,%3};"                 \
        : "+f"((d)[0]), "+f"((d)[1]), "+f"((d)[2]), "+f"((d)[3])                \
        : "r"(a0), "r"(a1), "r"(a2), "r"(a3), "r"(b0), "r"(b1))

// SW128 swizzle (128-byte rows)
__device__ __forceinline__ uint32_t swz(uint32_t off) { return off ^ ((off >> 3) & 0x70); }

// sortable-float encode/decode (ascending order == float order)
__device__ __forceinline__ unsigned f2sort(float f) {
    unsigned u = __float_as_uint(f);
    return (u & 0x80000000u) ? ~u : (u | 0x80000000u);
}
__device__ __forceinline__ float sort2f(unsigned u) {
    return __uint_as_float((u & 0x80000000u) ? (u & 0x7fffffffu) : ~u);
}
__device__ __forceinline__ unsigned pack_bf2(float x, float y) {
    __nv_bfloat162 h = __halves2bfloat162(__float2bfloat16(x), __float2bfloat16(y));
    return *(unsigned*)&h;
}

// ---------------------------------------------------------------------------
__global__ void k_init() {
    int t = blockIdx.x * blockDim.x + threadIdx.x;
    if (t < B_ROWS)  g_keys[t]  = 0xFFFFFFFFFFFFFFFFULL;
    if (t < E_CODES) g_counts[t] = 0;
    if (t == 0) { g_xnorm = 0.0; g_ncand = 0; }
}

// ---------------------------------------------------------------------------
__device__ __forceinline__ float block_reduce_sum(float v) {
    __shared__ float red[32];
    int lane = threadIdx.x & 31;
    int w    = threadIdx.x >> 5;
    #pragma unroll
    for (int o = 16; o > 0; o >>= 1) v += __shfl_down_sync(0xffffffffu, v, o);
    if (lane == 0) red[w] = v;
    __syncthreads();
    if (w == 0) {
        v = (lane < ((int)blockDim.x >> 5)) ? red[lane] : 0.0f;
        #pragma unroll
        for (int o = 16; o > 0; o >>= 1) v += __shfl_down_sync(0xffffffffu, v, o);
    }
    return v;
}

// ---------------------------------------------------------------------------
// fp32 -> bf16 for inputs and codebook (8 floats/thread, 16B stores);
// accumulate sum(x^2) over inputs.
__global__ void k_convert(const float* __restrict__ A, const float* __restrict__ Cb) {
    const size_t nA8 = (size_t)B_ROWS * DIM / 8;
    const size_t nB8 = (size_t)E_CODES * DIM / 8;
    const size_t gid = blockIdx.x * (size_t)blockDim.x + threadIdx.x;
    const size_t stride = (size_t)gridDim.x * blockDim.x;
    float xs = 0.0f;
    for (size_t j = gid; j < nA8; j += stride) {
        const float4* pa = (const float4*)A + 2 * j;
        float4 v0 = pa[0], v1 = pa[1];
        uint4 hp;
        hp.x = pack_bf2(v0.x, v0.y); hp.y = pack_bf2(v0.z, v0.w);
        hp.z = pack_bf2(v1.x, v1.y); hp.w = pack_bf2(v1.z, v1.w);
        *(uint4*)(g_Ah + 8 * j) = hp;
        xs += v0.x * v0.x + v0.y * v0.y + v0.z * v0.z + v0.w * v0.w
            + v1.x * v1.x + v1.y * v1.y + v1.z * v1.z + v1.w * v1.w;
    }
    for (size_t j = gid; j < nB8; j += stride) {
        const float4* pb = (const float4*)Cb + 2 * j;
        float4 v0 = pb[0], v1 = pb[1];
        uint4 hp;
        hp.x = pack_bf2(v0.x, v0.y); hp.y = pack_bf2(v0.z, v0.w);
        hp.z = pack_bf2(v1.x, v1.y); hp.w = pack_bf2(v1.z, v1.w);
        *(uint4*)(g_Bh + 8 * j) = hp;
    }
    float tot = block_reduce_sum(xs);
    if (threadIdx.x == 0) atomicAdd(&g_xnorm, (double)tot);
}

// ---------------------------------------------------------------------------
// ||e||^2 per codebook row (fp32, from original codebook; deterministic tree)
__global__ void k_cbnorm(const float* __restrict__ cb) {
    int e = blockIdx.x;
    const float4* row = (const float4*)(cb + (size_t)e * DIM);
    float s = 0.0f;
    for (int j = threadIdx.x; j < DIM / 4; j += blockDim.x) {
        float4 v = row[j];
        s += v.x * v.x + v.y * v.y + v.z * v.z + v.w * v.w;
    }
    float tot = block_reduce_sum(s);
    if (threadIdx.x == 0) g_cb_norm[e] = tot;
}

// ---------------------------------------------------------------------------
// bf16 GEMM via mma.sync (HMMA): dot(x_b, e_n) fp32 accum, single product.
// CTA tile 128x128, 8 warps (warp tile 32x64), KC=64, 3-stage cp.async.
#define MT      128
#define NT      128
#define KC      64
#define NSTAGE  3
#define KSLICE  (DIM / KSPLIT)               // 4096
#define ITERS   (KSLICE / KC)                // 64
#define TILE_B  (128 * 128)                  // 16 KB
#define STAGE_B (2 * TILE_B)                 // 32 KB
#define SMEM_TOTAL (NSTAGE * STAGE_B)        // 98304 B

__device__ __forceinline__ void load_stage(uint32_t sb, int st, int it, int m0, int n0,
                                           int kz, int tid) {
    const int kbase = kz + it * KC;
    #pragma unroll
    for (int j = 0; j < 8; j++) {
        int idx = tid + j * 256;             // 0..2047
        int t   = idx >> 10;                 // 0:A  1:B
        int w   = idx & 1023;
        int r   = w >> 3;                    // row 0..127
        int c   = w & 7;                     // 16B chunk within 128B row
        const __nv_bfloat16* src;
        if (t == 0) src = g_Ah + (size_t)(m0 + r) * DIM + kbase + c * 8;
        else        src = g_Bh + (size_t)(n0 + r) * DIM + kbase + c * 8;
        uint32_t dst = sb + st * STAGE_B + t * TILE_B + swz(r * 128 + c * 16);
        CP_ASYNC16(dst, src);
    }
}

__global__ void __launch_bounds__(256, 2) k_mma() {
    extern __shared__ __align__(128) char smem[];
    const uint32_t sb = smem_u32(smem);
    const int tid  = threadIdx.x;
    const int wid  = tid >> 5;
    const int lane = tid & 31;
    const int wm   = wid & 3;                // m block (32 rows)
    const int wn   = wid >> 2;               // n block (64 cols)
    const int m0   = blockIdx.x * MT;
    const int n0   = blockIdx.y * NT;
    const int kz   = blockIdx.z * KSLICE;

    float acc[2][8][4];
    #pragma unroll
    for (int mi = 0; mi < 2; mi++)
        #pragma unroll
        for (int nj = 0; nj < 8; nj++)
            #pragma unroll
            for (int q = 0; q < 4; q++) acc[mi][nj][q] = 0.0f;

    #pragma unroll
    for (int p = 0; p < NSTAGE - 1; p++) { load_stage(sb, p, p, m0, n0, kz, tid); CP_COMMIT(); }

    const uint32_t lrow = (lane & 15);
    const uint32_t lcol = (lane >> 4) * 16;

    for (int i = 0; i < ITERS; i++) {
        const int st = i % NSTAGE;
        CP_WAIT1();
        __syncthreads();
        if (i + NSTAGE - 1 < ITERS)
            load_stage(sb, (i + NSTAGE - 1) % NSTAGE, i + NSTAGE - 1, m0, n0, kz, tid);
        CP_COMMIT();

        const uint32_t s0 = sb + st * STAGE_B;
        #pragma unroll
        for (int ks = 0; ks < 4; ks++) {
            const uint32_t ko = ks * 32 + lcol;
            // issue ALL fragment loads first, then the 16 MMAs (one exposed
            // LDSM latency per ks instead of four)
            uint32_t a[2][4], b[4][4];
            #pragma unroll
            for (int mi = 0; mi < 2; mi++) {
                uint32_t ro = (wm * 32 + mi * 16 + lrow) * 128;
                LDSM_X4(a[mi], s0 + swz(ro + ko));
            }
            #pragma unroll
            for (int nq = 0; nq < 4; nq++) {
                uint32_t ro = (wn * 64 + nq * 16 + lrow) * 128;
                LDSM_X4(b[nq], s0 + TILE_B + swz(ro + ko));
            }
            #pragma unroll
            for (int nq = 0; nq < 4; nq++)
                #pragma unroll
                for (int mi = 0; mi < 2; mi++) {
                    MMA_BF16(acc[mi][2 * nq],     a[mi][0], a[mi][1], a[mi][2], a[mi][3],
                             b[nq][0], b[nq][2]);
                    MMA_BF16(acc[mi][2 * nq + 1], a[mi][0], a[mi][1], a[mi][2], a[mi][3],
                             b[nq][1], b[nq][3]);
                }
        }
    }

    // epilogue: write partial dots
    #pragma unroll
    for (int mi = 0; mi < 2; mi++) {
        #pragma unroll
        for (int nj = 0; nj < 8; nj++) {
            int row = m0 + wm * 32 + mi * 16 + (lane >> 2);
            int col = n0 + wn * 64 + nj * 8 + (lane & 3) * 2;
            float* d = &g_Dpart[((size_t)blockIdx.z * B_ROWS + row) * E_CODES + col];
            *(float2*)d = make_float2(acc[mi][nj][0], acc[mi][nj][1]);
            *(float2*)(d + 8 * E_CODES) = make_float2(acc[mi][nj][2], acc[mi][nj][3]);
        }
    }
}

// ---------------------------------------------------------------------------
// bf16 argmin per row + near-tie candidate extraction (one warp per row)
__global__ void k_argmin() {
    const int row  = blockIdx.x * 8 + (threadIdx.x >> 5);
    const int lane = threadIdx.x & 31;
    const size_t SL = (size_t)B_ROWS * E_CODES;
    const float* d = &g_Dpart[(size_t)row * E_CODES];
    float s[16];
    float m = 3.4e38f;
    #pragma unroll
    for (int j = 0; j < 16; j++) {
        int e = j * 32 + lane;
        float dot = 0.0f;
        #pragma unroll
        for (int z = 0; z < KSPLIT; z++) dot += d[z * SL + e];
        s[j] = g_cb_norm[e] - 2.0f * dot;
        m = fminf(m, s[j]);
    }
    #pragma unroll
    for (int o = 16; o > 0; o >>= 1) m = fminf(m, __shfl_xor_sync(0xffffffffu, m, o));

    int cnt = 0;
    #pragma unroll
    for (int j = 0; j < 16; j++) cnt += (s[j] <= m + TH);
    #pragma unroll
    for (int o = 16; o > 0; o >>= 1) cnt += __shfl_xor_sync(0xffffffffu, cnt, o);

    if (cnt == 1) {
        int be = 0x7fffffff;
        #pragma unroll
        for (int j = 0; j < 16; j++) if (s[j] <= m + TH) be = j * 32 + lane;
        #pragma unroll
        for (int o = 16; o > 0; o >>= 1) be = min(be, __shfl_xor_sync(0xffffffffu, be, o));
        if (lane == 0)
            g_keys[row] = ((unsigned long long)f2sort(m) << 32) | (unsigned)be;
    } else {
        #pragma unroll
        for (int j = 0; j < 16; j++) {
            if (s[j] <= m + TH) {
                int e = j * 32 + lane;
                int slot = atomicAdd(&g_ncand, 1);
                if (slot < MAXCAND) g_cand[slot] = ((unsigned)row << 9) | (unsigned)e;
            }
        }
    }
}

// ---------------------------------------------------------------------------
// exact fp32 re-score of near-tie candidates; atomicMin sortable keys
__global__ void k_refine(const float* __restrict__ A, const float* __restrict__ Cb) {
    const int n = g_ncand;
    for (int j = blockIdx.x; j < n && j < MAXCAND; j += gridDim.x) {
        uint32_t cd  = g_cand[j];
        int row  = cd >> 9;
        int code = cd & 511;
        const float4* x = (const float4*)(A  + (size_t)row  * DIM);
        const float4* e = (const float4*)(Cb + (size_t)code * DIM);
        float dot = 0.0f;
        for (int i = threadIdx.x; i < DIM / 4; i += blockDim.x) {
            float4 xv = x[i], ev = e[i];
            dot += xv.x * ev.x + xv.y * ev.y + xv.z * ev.z + xv.w * ev.w;
        }
        float tot = block_reduce_sum(dot);
        if (threadIdx.x == 0) {
            float sc = g_cb_norm[code] - 2.0f * tot;
            unsigned long long key = ((unsigned long long)f2sort(sc) << 32) | (unsigned)code;
            atomicMin(&g_keys[row], key);
        }
        __syncthreads();
    }
}

// ---------------------------------------------------------------------------
// per row b: one-hot enc row + histogram + gather codebook row (vectorized).
// q-region starts at out+1 (element offset ≡1 mod 4): 3-elem prefix, shifted
// float4 bulk, 1-elem tail.
__global__ void k_gather(const float* __restrict__ Cb, float* __restrict__ out) {
    int b   = blockIdx.x;
    int idx = (int)(g_keys[b] & 0xFFFFFFFFu);

    // encodings row: zero 512 floats with float2, then set one-hot
    float2* enc = (float2*)(out + OFF_ENC + (size_t)b * E_CODES);
    if (threadIdx.x < 256) enc[threadIdx.x] = make_float2(0.f, 0.f);
    __syncthreads();
    if (threadIdx.x == 0) {
        out[OFF_ENC + (size_t)b * E_CODES + idx] = 1.0f;
        atomicAdd(&g_counts[idx], 1);
    }

    const float*  q  = Cb + (size_t)idx * DIM;
    const float4* q4 = (const float4*)q;
    float* o = out + OFF_Q + (size_t)b * DIM;
    if (threadIdx.x < 3) o[threadIdx.x] = q[threadIdx.x];        // prefix 0..2
    if (threadIdx.x == 3) o[DIM - 1] = q[DIM - 1];               // tail 16383
    float4* o4 = (float4*)(o + 3);                               // 16B aligned
    for (int t = threadIdx.x; t < (DIM - 4) / 4; t += blockDim.x) {
        float4 s0 = q4[t];
        float4 s1 = q4[t + 1];
        o4[t] = make_float4(s0.w, s1.x, s1.y, s1.z);
    }
}

// ---------------------------------------------------------------------------
// loss from Sum(best scores) + Sum(x^2); perplexity from counts
__global__ void k_finalize(float* __restrict__ out) {
    __shared__ double sh[512];
    int t = threadIdx.x;

    double s = 0.0;
    for (int r = t; r < B_ROWS; r += 512)
        s += (double)sort2f((unsigned)(g_keys[r] >> 32));
    sh[t] = s;
    __syncthreads();
    for (int k = 256; k > 0; k >>= 1) {
        if (t < k) sh[t] += sh[t + k];
        __syncthreads();
    }
    double score_sum = sh[0];
    __syncthreads();

    float p = (float)g_counts[t] / (float)B_ROWS;
    sh[t] = (double)(p * logf(p + 1e-10f));
    __syncthreads();
    for (int k = 256; k > 0; k >>= 1) {
        if (t < k) sh[t] += sh[t + k];
        __syncthreads();
    }
    if (t == 0) {
        out[OFF_PERP] = expf(-(float)sh[0]);
        double mse = (score_sum + g_xnorm) / ((double)B_ROWS * (double)DIM);
        out[OFF_LOSS] = (float)(1.25 * mse);
    }
}

// ---------------------------------------------------------------------------
extern "C" void kernel_launch(void* const* d_in, const int* in_sizes, int n_in,
                              void* d_out, int out_size) {
    const float* inputs   = (const float*)d_in[0];   // [2048, 16384]
    const float* codebook = (const float*)d_in[1];   // [512, 16384]
    float* out = (float*)d_out;
    (void)in_sizes; (void)n_in; (void)out_size;

    static int smem_set = 0;
    if (!smem_set) {
        cudaFuncSetAttribute(k_mma, cudaFuncAttributeMaxDynamicSharedMemorySize, SMEM_TOTAL);
        smem_set = 1;
    }

    k_init<<<8, 256>>>();
    k_convert<<<2048, 256>>>(inputs, codebook);
    k_cbnorm<<<E_CODES, 256>>>(codebook);

    dim3 grid(B_ROWS / MT, E_CODES / NT, KSPLIT);    // (16, 4, 4) = 256 CTAs
    k_mma<<<grid, 256, SMEM_TOTAL>>>();

    k_argmin<<<B_ROWS / 8, 256>>>();
    k_refine<<<1024, 256>>>(inputs, codebook);
    k_gather<<<B_ROWS, 256>>>(codebook, out);
    k_finalize<<<1, 512>>>(out);
}